// round 1
// baseline (speedup 1.0000x reference)
#include <cuda_runtime.h>
#include <math.h>

#define TLEN 32768
#define NB 2
#define RC 64
#define GC 128
#define SC 64
#define AC 80
#define NLAYERS 30
#define KTOT 272          // 192 (dilated taps) + 80 (cond)
#define TN 128            // time tile per block
#define SQRT_HALF 0.70710678118654752440f
#define SQRT_INV_L 0.18257418583505537115f

// ---------------- scratch (static device globals; no cudaMalloc) -------------
__device__ float g_cup [NB * AC * TLEN];   // upsampled conditioning (B,80,T)
__device__ float g_h0  [NB * RC * TLEN];   // residual ping
__device__ float g_h1  [NB * RC * TLEN];   // residual pong
__device__ float g_skip[NB * SC * TLEN];   // skip accumulator
__device__ float g_tmpA[NB * AC * 8192];   // upsample scratch
__device__ float g_tmpB[NB * AC * 8192];

// ---------------- conditioning 1x1: tmp[b,o,f] = sum_i Wc[o,i] c[b,i,f] ------
__global__ void cin_kernel(const float* __restrict__ c,
                           const float* __restrict__ Wc,
                           float* __restrict__ out)
{
    int idx = blockIdx.x * blockDim.x + threadIdx.x;
    if (idx >= NB * AC * 128) return;
    int f = idx & 127;
    int o = (idx >> 7) % AC;
    int b = idx / (128 * AC);
    const float* cb = c + b * AC * 128;
    float acc = 0.f;
    #pragma unroll 4
    for (int i = 0; i < AC; ++i)
        acc += Wc[o * AC + i] * cb[i * 128 + f];
    out[idx] = acc;
}

// ---------------- one upsample stage: repeat x4 then 9-tap conv (pad 4) ------
__global__ void up_kernel(const float* __restrict__ in,
                          float* __restrict__ out,
                          int Lin,
                          const float* __restrict__ w9)
{
    int Lout = Lin * 4;
    int N = NB * AC * Lout;
    int idx = blockIdx.x * blockDim.x + threadIdx.x;
    if (idx >= N) return;
    int t  = idx % Lout;
    int bc = idx / Lout;
    const float* inb = in + bc * Lin;
    float w[9];
    #pragma unroll
    for (int k = 0; k < 9; ++k) w[k] = w9[k];
    float acc = 0.f;
    #pragma unroll
    for (int k = 0; k < 9; ++k) {
        int j = t - 4 + k;             // index into the repeated (un-padded) signal
        if (j >= 0 && j < Lout)
            acc += w[k] * inb[j >> 2];
    }
    out[idx] = acc;
}

// ---------------- first conv + zero skip accumulator -------------------------
__global__ void first_kernel(const float* __restrict__ x,
                             const float* __restrict__ Wf,
                             const float* __restrict__ bf,
                             float* __restrict__ h,
                             float* __restrict__ skip)
{
    int idx = blockIdx.x * blockDim.x + threadIdx.x;
    if (idx >= NB * RC * TLEN) return;
    int t = idx & (TLEN - 1);
    int r = (idx / TLEN) % RC;
    int b = idx / (TLEN * RC);
    h[idx]    = Wf[r] * x[b * TLEN + t] + bf[r];
    skip[idx] = 0.f;
}

// ---------------- fused residual layer ---------------------------------------
// GEMM1: g(128 x TN) = [Wd | Wa](128 x 272) * B(272 x TN), B gathers h taps + cup
// gate:  z = tanh(g[0:64]) * sigmoid(g[64:128])
// GEMM2: [skip_add; res](128 x TN) = [Ws; Wr](128 x 64) * z
// epilogue: skip += skip_add + bs ; h_out = (res + br + h_in) * sqrt(0.5)
__global__ __launch_bounds__(256, 2)
void layer_kernel(const float* __restrict__ Wd,  const float* __restrict__ bd,
                  const float* __restrict__ Wa,  const float* __restrict__ Ws,
                  const float* __restrict__ bs,  const float* __restrict__ Wr,
                  const float* __restrict__ br,
                  const float* __restrict__ hin, float* __restrict__ hout,
                  const float* __restrict__ cup, float* __restrict__ skip,
                  int layer, int dil)
{
    __shared__ float As[8][128];      // weight chunk, [kk][out-channel]
    __shared__ float Bs[8][TN];       // data chunk,   [kk][n]
    __shared__ float zs[64][TN];      // gated activations

    const int tid = threadIdx.x;
    const int tx  = tid & 15;         // 0..15 -> n
    const int ty  = tid >> 4;         // 0..15 -> m
    const int n0  = tx * 8;
    const int r0  = ty * 4;           // rows r0..r0+3 and r0+64..r0+67
    const int b   = blockIdx.y;
    const int t0  = blockIdx.x * TN;

    const float* Wd_l = Wd + (size_t)layer * GC * RC * 3;   // [o][r*3+tap]
    const float* Wa_l = Wa + (size_t)layer * GC * AC;       // [o][a]

    float acc[8][8];
    #pragma unroll
    for (int i = 0; i < 8; ++i)
        #pragma unroll
        for (int j = 0; j < 8; ++j) acc[i][j] = 0.f;

    // ---- GEMM1: K = 272 in chunks of 8 ----
    for (int k0 = 0; k0 < KTOT; k0 += 8) {
        __syncthreads();
        // stage A (128 x 8 weights)
        #pragma unroll
        for (int it = 0; it < 4; ++it) {
            int idx = it * 256 + tid;
            int kk = idx >> 7;
            int o  = idx & 127;
            int k  = k0 + kk;
            float v = (k < 192) ? Wd_l[o * 192 + k]
                                : Wa_l[o * AC + (k - 192)];
            As[kk][o] = v;
        }
        // stage B (8 x 128 data gather)
        #pragma unroll
        for (int it = 0; it < 4; ++it) {
            int idx = it * 256 + tid;
            int kk = idx >> 7;
            int n  = idx & 127;
            int k  = k0 + kk;
            int t  = t0 + n;
            float v;
            if (k < 192) {
                int r   = k / 3;
                int tap = k - r * 3;
                int tt  = t + (tap - 1) * dil;
                v = (tt >= 0 && tt < TLEN) ? hin[((size_t)b * RC + r) * TLEN + tt] : 0.f;
            } else {
                v = cup[((size_t)b * AC + (k - 192)) * TLEN + t];
            }
            Bs[kk][n] = v;
        }
        __syncthreads();
        #pragma unroll
        for (int kk = 0; kk < 8; ++kk) {
            float a[8], bb[8];
            *(float4*)&a[0]  = *(const float4*)&As[kk][r0];
            *(float4*)&a[4]  = *(const float4*)&As[kk][64 + r0];
            *(float4*)&bb[0] = *(const float4*)&Bs[kk][n0];
            *(float4*)&bb[4] = *(const float4*)&Bs[kk][n0 + 4];
            #pragma unroll
            for (int mi = 0; mi < 8; ++mi)
                #pragma unroll
                for (int ni = 0; ni < 8; ++ni)
                    acc[mi][ni] += a[mi] * bb[ni];
        }
    }

    // ---- gate: z = tanh(xa) * sigmoid(xb) ----
    {
        const float* bd_l = bd + layer * GC;
        #pragma unroll
        for (int mi = 0; mi < 4; ++mi) {
            float ba = bd_l[r0 + mi];
            float bb_ = bd_l[64 + r0 + mi];
            #pragma unroll
            for (int ni = 0; ni < 8; ++ni) {
                float xa = acc[mi][ni] + ba;
                float xb = acc[mi + 4][ni] + bb_;
                float z = tanhf(xa) * (1.f / (1.f + expf(-xb)));
                zs[r0 + mi][n0 + ni] = z;
            }
        }
    }

    // ---- GEMM2: [Ws; Wr](128 x 64) * z ----
    float acc2[8][8];
    #pragma unroll
    for (int i = 0; i < 8; ++i)
        #pragma unroll
        for (int j = 0; j < 8; ++j) acc2[i][j] = 0.f;

    const float* Ws_l = Ws + (size_t)layer * SC * (GC / 2);
    const float* Wr_l = Wr + (size_t)layer * RC * (GC / 2);

    for (int k0 = 0; k0 < 64; k0 += 8) {
        __syncthreads();
        #pragma unroll
        for (int it = 0; it < 4; ++it) {
            int idx = it * 256 + tid;
            int kk = idx >> 7;
            int o  = idx & 127;
            int k  = k0 + kk;
            float v = (o < 64) ? Ws_l[o * 64 + k] : Wr_l[(o - 64) * 64 + k];
            As[kk][o] = v;
        }
        __syncthreads();
        #pragma unroll
        for (int kk = 0; kk < 8; ++kk) {
            float a[8], bb[8];
            *(float4*)&a[0]  = *(const float4*)&As[kk][r0];
            *(float4*)&a[4]  = *(const float4*)&As[kk][64 + r0];
            *(float4*)&bb[0] = *(const float4*)&zs[k0 + kk][n0];
            *(float4*)&bb[4] = *(const float4*)&zs[k0 + kk][n0 + 4];
            #pragma unroll
            for (int mi = 0; mi < 8; ++mi)
                #pragma unroll
                for (int ni = 0; ni < 8; ++ni)
                    acc2[mi][ni] += a[mi] * bb[ni];
        }
    }

    // ---- epilogue ----
    {
        const float* bs_l = bs + layer * SC;
        const float* br_l = br + layer * RC;
        #pragma unroll
        for (int mi = 0; mi < 4; ++mi) {
            int ch = r0 + mi;
            float bsv = bs_l[ch];
            float brv = br_l[ch];
            size_t soff = ((size_t)b * SC + ch) * TLEN + t0 + n0;
            size_t hoff = ((size_t)b * RC + ch) * TLEN + t0 + n0;
            #pragma unroll
            for (int ni = 0; ni < 8; ++ni) {
                skip[soff + ni] += acc2[mi][ni] + bsv;
                hout[hoff + ni]  = (acc2[4 + mi][ni] + brv + hin[hoff + ni]) * SQRT_HALF;
            }
        }
    }
}

// ---------------- final head: relu -> 1x1 -> relu -> 1x1 ---------------------
__global__ void final_kernel(const float* __restrict__ skip,
                             const float* __restrict__ Wl1,
                             const float* __restrict__ bl1,
                             const float* __restrict__ Wl2,
                             const float* __restrict__ bl2,
                             float* __restrict__ out)
{
    __shared__ float W1s[64 * 64];
    __shared__ float b1s[64];
    __shared__ float W2s[64];
    int tid = threadIdx.x;
    for (int i = tid; i < 64 * 64; i += blockDim.x) W1s[i] = Wl1[i];
    if (tid < 64) { b1s[tid] = bl1[tid]; W2s[tid] = Wl2[tid]; }
    __syncthreads();

    int idx = blockIdx.x * blockDim.x + tid;
    if (idx >= NB * TLEN) return;
    int t = idx & (TLEN - 1);
    int b = idx / TLEN;

    float s1[64];
    #pragma unroll 8
    for (int j = 0; j < 64; ++j) {
        float v = skip[((size_t)b * SC + j) * TLEN + t] * SQRT_INV_L;
        s1[j] = fmaxf(v, 0.f);
    }
    float y2 = bl2[0];
    #pragma unroll 2
    for (int o = 0; o < 64; ++o) {
        float a = b1s[o];
        #pragma unroll 8
        for (int j = 0; j < 64; ++j) a += W1s[o * 64 + j] * s1[j];
        y2 += W2s[o] * fmaxf(a, 0.f);
    }
    out[(size_t)b * TLEN + t] = y2;
}

// ---------------- launch ------------------------------------------------------
extern "C" void kernel_launch(void* const* d_in, const int* in_sizes, int n_in,
                              void* d_out, int out_size)
{
    const float* x       = (const float*)d_in[0];
    const float* c       = (const float*)d_in[1];
    const float* W_first = (const float*)d_in[2];
    const float* b_first = (const float*)d_in[3];
    const float* W_cin   = (const float*)d_in[4];
    const float* W_up    = (const float*)d_in[5];
    const float* Wd      = (const float*)d_in[6];
    const float* bd      = (const float*)d_in[7];
    const float* Wa      = (const float*)d_in[8];
    const float* Ws      = (const float*)d_in[9];
    const float* bs      = (const float*)d_in[10];
    const float* Wr      = (const float*)d_in[11];
    const float* br      = (const float*)d_in[12];
    const float* Wl1     = (const float*)d_in[13];
    const float* bl1     = (const float*)d_in[14];
    const float* Wl2     = (const float*)d_in[15];
    const float* bl2     = (const float*)d_in[16];
    float* out = (float*)d_out;

    float *cup, *h0, *h1, *skip, *tA, *tB;
    cudaGetSymbolAddress((void**)&cup,  g_cup);
    cudaGetSymbolAddress((void**)&h0,   g_h0);
    cudaGetSymbolAddress((void**)&h1,   g_h1);
    cudaGetSymbolAddress((void**)&skip, g_skip);
    cudaGetSymbolAddress((void**)&tA,   g_tmpA);
    cudaGetSymbolAddress((void**)&tB,   g_tmpB);

    // conditioning pipeline: 1x1 then 4 upsample stages (x4 each)
    {
        int N = NB * AC * 128;
        cin_kernel<<<(N + 255) / 256, 256>>>(c, W_cin, tA);
    }
    {
        int Lin = 128, N = NB * AC * Lin * 4;
        up_kernel<<<(N + 255) / 256, 256>>>(tA, tB, Lin, W_up + 0);
    }
    {
        int Lin = 512, N = NB * AC * Lin * 4;
        up_kernel<<<(N + 255) / 256, 256>>>(tB, tA, Lin, W_up + 9);
    }
    {
        int Lin = 2048, N = NB * AC * Lin * 4;
        up_kernel<<<(N + 255) / 256, 256>>>(tA, tB, Lin, W_up + 18);
    }
    {
        int Lin = 8192, N = NB * AC * Lin * 4;
        up_kernel<<<(N + 255) / 256, 256>>>(tB, cup, Lin, W_up + 27);
    }

    // first conv + zero skips
    {
        int N = NB * RC * TLEN;
        first_kernel<<<(N + 255) / 256, 256>>>(x, W_first, b_first, h0, skip);
    }

    // 30 residual layers, ping-pong h
    float* hin = h0;
    float* hout = h1;
    dim3 grid(TLEN / TN, NB);
    for (int i = 0; i < NLAYERS; ++i) {
        int d = 1 << (i % 10);
        layer_kernel<<<grid, 256>>>(Wd, bd, Wa, Ws, bs, Wr, br,
                                    hin, hout, cup, skip, i, d);
        float* tmp = hin; hin = hout; hout = tmp;
    }

    // head
    {
        int N = NB * TLEN;
        final_kernel<<<(N + 255) / 256, 256>>>(skip, Wl1, bl1, Wl2, bl2, out);
    }
}

// round 2
// speedup vs baseline: 1.0007x; 1.0007x over previous
#include <cuda_runtime.h>
#include <math.h>

#define TLEN 32768
#define NB 2
#define RC 64
#define GC 128
#define SC 64
#define AC 80
#define NLAYERS 30
#define KTOT 272          // 192 (dilated taps) + 80 (cond)
#define TN 128            // time tile per block
#define SQRT_HALF 0.70710678118654752440f
#define SQRT_INV_L 0.18257418583505537115f

// ---------------- scratch (static device globals; no cudaMalloc) -------------
__device__ float g_cup [NB * AC * TLEN];   // upsampled conditioning (B,80,T)
__device__ float g_h0  [NB * RC * TLEN];   // residual ping
__device__ float g_h1  [NB * RC * TLEN];   // residual pong
__device__ float g_skip[NB * SC * TLEN];   // skip accumulator
__device__ float g_tmpA[NB * AC * 8192];   // upsample scratch
__device__ float g_tmpB[NB * AC * 8192];

// ---------------- conditioning 1x1: tmp[b,o,f] = sum_i Wc[o,i] c[b,i,f] ------
__global__ void cin_kernel(const float* __restrict__ c,
                           const float* __restrict__ Wc,
                           float* __restrict__ out)
{
    int idx = blockIdx.x * blockDim.x + threadIdx.x;
    if (idx >= NB * AC * 128) return;
    int f = idx & 127;
    int o = (idx >> 7) % AC;
    int b = idx / (128 * AC);
    const float* cb = c + b * AC * 128;
    float acc = 0.f;
    #pragma unroll 4
    for (int i = 0; i < AC; ++i)
        acc += Wc[o * AC + i] * cb[i * 128 + f];
    out[idx] = acc;
}

// ---------------- one upsample stage: repeat x4 then 9-tap conv (pad 4) ------
__global__ void up_kernel(const float* __restrict__ in,
                          float* __restrict__ out,
                          int Lin,
                          const float* __restrict__ w9)
{
    int Lout = Lin * 4;
    int N = NB * AC * Lout;
    int idx = blockIdx.x * blockDim.x + threadIdx.x;
    if (idx >= N) return;
    int t  = idx % Lout;
    int bc = idx / Lout;
    const float* inb = in + bc * Lin;
    float w[9];
    #pragma unroll
    for (int k = 0; k < 9; ++k) w[k] = w9[k];
    float acc = 0.f;
    #pragma unroll
    for (int k = 0; k < 9; ++k) {
        int j = t - 4 + k;             // index into the repeated (un-padded) signal
        if (j >= 0 && j < Lout)
            acc += w[k] * inb[j >> 2];
    }
    out[idx] = acc;
}

// ---------------- first conv + zero skip accumulator -------------------------
__global__ void first_kernel(const float* __restrict__ x,
                             const float* __restrict__ Wf,
                             const float* __restrict__ bf,
                             float* __restrict__ h,
                             float* __restrict__ skip)
{
    int idx = blockIdx.x * blockDim.x + threadIdx.x;
    if (idx >= NB * RC * TLEN) return;
    int t = idx & (TLEN - 1);
    int r = (idx / TLEN) % RC;
    int b = idx / (TLEN * RC);
    h[idx]    = Wf[r] * x[b * TLEN + t] + bf[r];
    skip[idx] = 0.f;
}

// ---------------- fused residual layer ---------------------------------------
// GEMM1: g(128 x TN) = [Wd | Wa](128 x 272) * B(272 x TN), B gathers h taps + cup
// gate:  z = tanh(g[0:64]) * sigmoid(g[64:128])
// GEMM2: [skip_add; res](128 x TN) = [Ws; Wr](128 x 64) * z
// epilogue: skip += skip_add + bs ; h_out = (res + br + h_in) * sqrt(0.5)
__global__ __launch_bounds__(256, 2)
void layer_kernel(const float* __restrict__ Wd,  const float* __restrict__ bd,
                  const float* __restrict__ Wa,  const float* __restrict__ Ws,
                  const float* __restrict__ bs,  const float* __restrict__ Wr,
                  const float* __restrict__ br,
                  const float* __restrict__ hin, float* __restrict__ hout,
                  const float* __restrict__ cup, float* __restrict__ skip,
                  int layer, int dil)
{
    __shared__ float As[8][128];      // weight chunk, [kk][out-channel]
    __shared__ float Bs[8][TN];       // data chunk,   [kk][n]
    __shared__ float zs[64][TN];      // gated activations

    const int tid = threadIdx.x;
    const int tx  = tid & 15;         // 0..15 -> n
    const int ty  = tid >> 4;         // 0..15 -> m
    const int n0  = tx * 8;
    const int r0  = ty * 4;           // rows r0..r0+3 and r0+64..r0+67
    const int b   = blockIdx.y;
    const int t0  = blockIdx.x * TN;

    const float* Wd_l = Wd + (size_t)layer * GC * RC * 3;   // [o][r*3+tap]
    const float* Wa_l = Wa + (size_t)layer * GC * AC;       // [o][a]

    float acc[8][8];
    #pragma unroll
    for (int i = 0; i < 8; ++i)
        #pragma unroll
        for (int j = 0; j < 8; ++j) acc[i][j] = 0.f;

    // ---- GEMM1: K = 272 in chunks of 8 ----
    for (int k0 = 0; k0 < KTOT; k0 += 8) {
        __syncthreads();
        // stage A (128 x 8 weights)
        #pragma unroll
        for (int it = 0; it < 4; ++it) {
            int idx = it * 256 + tid;
            int kk = idx >> 7;
            int o  = idx & 127;
            int k  = k0 + kk;
            float v = (k < 192) ? Wd_l[o * 192 + k]
                                : Wa_l[o * AC + (k - 192)];
            As[kk][o] = v;
        }
        // stage B (8 x 128 data gather)
        #pragma unroll
        for (int it = 0; it < 4; ++it) {
            int idx = it * 256 + tid;
            int kk = idx >> 7;
            int n  = idx & 127;
            int k  = k0 + kk;
            int t  = t0 + n;
            float v;
            if (k < 192) {
                int r   = k / 3;
                int tap = k - r * 3;
                int tt  = t + (tap - 1) * dil;
                v = (tt >= 0 && tt < TLEN) ? hin[((size_t)b * RC + r) * TLEN + tt] : 0.f;
            } else {
                v = cup[((size_t)b * AC + (k - 192)) * TLEN + t];
            }
            Bs[kk][n] = v;
        }
        __syncthreads();
        #pragma unroll
        for (int kk = 0; kk < 8; ++kk) {
            float a[8], bb[8];
            *(float4*)&a[0]  = *(const float4*)&As[kk][r0];
            *(float4*)&a[4]  = *(const float4*)&As[kk][64 + r0];
            *(float4*)&bb[0] = *(const float4*)&Bs[kk][n0];
            *(float4*)&bb[4] = *(const float4*)&Bs[kk][n0 + 4];
            #pragma unroll
            for (int mi = 0; mi < 8; ++mi)
                #pragma unroll
                for (int ni = 0; ni < 8; ++ni)
                    acc[mi][ni] += a[mi] * bb[ni];
        }
    }

    // ---- gate: z = tanh(xa) * sigmoid(xb) ----
    {
        const float* bd_l = bd + layer * GC;
        #pragma unroll
        for (int mi = 0; mi < 4; ++mi) {
            float ba = bd_l[r0 + mi];
            float bb_ = bd_l[64 + r0 + mi];
            #pragma unroll
            for (int ni = 0; ni < 8; ++ni) {
                float xa = acc[mi][ni] + ba;
                float xb = acc[mi + 4][ni] + bb_;
                float z = tanhf(xa) * (1.f / (1.f + expf(-xb)));
                zs[r0 + mi][n0 + ni] = z;
            }
        }
    }

    // ---- GEMM2: [Ws; Wr](128 x 64) * z ----
    float acc2[8][8];
    #pragma unroll
    for (int i = 0; i < 8; ++i)
        #pragma unroll
        for (int j = 0; j < 8; ++j) acc2[i][j] = 0.f;

    const float* Ws_l = Ws + (size_t)layer * SC * (GC / 2);
    const float* Wr_l = Wr + (size_t)layer * RC * (GC / 2);

    for (int k0 = 0; k0 < 64; k0 += 8) {
        __syncthreads();
        #pragma unroll
        for (int it = 0; it < 4; ++it) {
            int idx = it * 256 + tid;
            int kk = idx >> 7;
            int o  = idx & 127;
            int k  = k0 + kk;
            float v = (o < 64) ? Ws_l[o * 64 + k] : Wr_l[(o - 64) * 64 + k];
            As[kk][o] = v;
        }
        __syncthreads();
        #pragma unroll
        for (int kk = 0; kk < 8; ++kk) {
            float a[8], bb[8];
            *(float4*)&a[0]  = *(const float4*)&As[kk][r0];
            *(float4*)&a[4]  = *(const float4*)&As[kk][64 + r0];
            *(float4*)&bb[0] = *(const float4*)&zs[k0 + kk][n0];
            *(float4*)&bb[4] = *(const float4*)&zs[k0 + kk][n0 + 4];
            #pragma unroll
            for (int mi = 0; mi < 8; ++mi)
                #pragma unroll
                for (int ni = 0; ni < 8; ++ni)
                    acc2[mi][ni] += a[mi] * bb[ni];
        }
    }

    // ---- epilogue ----
    {
        const float* bs_l = bs + layer * SC;
        const float* br_l = br + layer * RC;
        #pragma unroll
        for (int mi = 0; mi < 4; ++mi) {
            int ch = r0 + mi;
            float bsv = bs_l[ch];
            float brv = br_l[ch];
            size_t soff = ((size_t)b * SC + ch) * TLEN + t0 + n0;
            size_t hoff = ((size_t)b * RC + ch) * TLEN + t0 + n0;
            #pragma unroll
            for (int ni = 0; ni < 8; ++ni) {
                skip[soff + ni] += acc2[mi][ni] + bsv;
                hout[hoff + ni]  = (acc2[4 + mi][ni] + brv + hin[hoff + ni]) * SQRT_HALF;
            }
        }
    }
}

// ---------------- final head: relu -> 1x1 -> relu -> 1x1 ---------------------
__global__ void final_kernel(const float* __restrict__ skip,
                             const float* __restrict__ Wl1,
                             const float* __restrict__ bl1,
                             const float* __restrict__ Wl2,
                             const float* __restrict__ bl2,
                             float* __restrict__ out)
{
    __shared__ float W1s[64 * 64];
    __shared__ float b1s[64];
    __shared__ float W2s[64];
    int tid = threadIdx.x;
    for (int i = tid; i < 64 * 64; i += blockDim.x) W1s[i] = Wl1[i];
    if (tid < 64) { b1s[tid] = bl1[tid]; W2s[tid] = Wl2[tid]; }
    __syncthreads();

    int idx = blockIdx.x * blockDim.x + tid;
    if (idx >= NB * TLEN) return;
    int t = idx & (TLEN - 1);
    int b = idx / TLEN;

    float s1[64];
    #pragma unroll 8
    for (int j = 0; j < 64; ++j) {
        float v = skip[((size_t)b * SC + j) * TLEN + t] * SQRT_INV_L;
        s1[j] = fmaxf(v, 0.f);
    }
    float y2 = bl2[0];
    #pragma unroll 2
    for (int o = 0; o < 64; ++o) {
        float a = b1s[o];
        #pragma unroll 8
        for (int j = 0; j < 64; ++j) a += W1s[o * 64 + j] * s1[j];
        y2 += W2s[o] * fmaxf(a, 0.f);
    }
    out[(size_t)b * TLEN + t] = y2;
}

// ---------------- launch ------------------------------------------------------
extern "C" void kernel_launch(void* const* d_in, const int* in_sizes, int n_in,
                              void* d_out, int out_size)
{
    const float* x       = (const float*)d_in[0];
    const float* c       = (const float*)d_in[1];
    const float* W_first = (const float*)d_in[2];
    const float* b_first = (const float*)d_in[3];
    const float* W_cin   = (const float*)d_in[4];
    const float* W_up    = (const float*)d_in[5];
    const float* Wd      = (const float*)d_in[6];
    const float* bd      = (const float*)d_in[7];
    const float* Wa      = (const float*)d_in[8];
    const float* Ws      = (const float*)d_in[9];
    const float* bs      = (const float*)d_in[10];
    const float* Wr      = (const float*)d_in[11];
    const float* br      = (const float*)d_in[12];
    const float* Wl1     = (const float*)d_in[13];
    const float* bl1     = (const float*)d_in[14];
    const float* Wl2     = (const float*)d_in[15];
    const float* bl2     = (const float*)d_in[16];
    float* out = (float*)d_out;

    float *cup, *h0, *h1, *skip, *tA, *tB;
    cudaGetSymbolAddress((void**)&cup,  g_cup);
    cudaGetSymbolAddress((void**)&h0,   g_h0);
    cudaGetSymbolAddress((void**)&h1,   g_h1);
    cudaGetSymbolAddress((void**)&skip, g_skip);
    cudaGetSymbolAddress((void**)&tA,   g_tmpA);
    cudaGetSymbolAddress((void**)&tB,   g_tmpB);

    // conditioning pipeline: 1x1 then 4 upsample stages (x4 each)
    {
        int N = NB * AC * 128;
        cin_kernel<<<(N + 255) / 256, 256>>>(c, W_cin, tA);
    }
    {
        int Lin = 128, N = NB * AC * Lin * 4;
        up_kernel<<<(N + 255) / 256, 256>>>(tA, tB, Lin, W_up + 0);
    }
    {
        int Lin = 512, N = NB * AC * Lin * 4;
        up_kernel<<<(N + 255) / 256, 256>>>(tB, tA, Lin, W_up + 9);
    }
    {
        int Lin = 2048, N = NB * AC * Lin * 4;
        up_kernel<<<(N + 255) / 256, 256>>>(tA, tB, Lin, W_up + 18);
    }
    {
        int Lin = 8192, N = NB * AC * Lin * 4;
        up_kernel<<<(N + 255) / 256, 256>>>(tB, cup, Lin, W_up + 27);
    }

    // first conv + zero skips
    {
        int N = NB * RC * TLEN;
        first_kernel<<<(N + 255) / 256, 256>>>(x, W_first, b_first, h0, skip);
    }

    // 30 residual layers, ping-pong h
    float* hin = h0;
    float* hout = h1;
    dim3 grid(TLEN / TN, NB);
    for (int i = 0; i < NLAYERS; ++i) {
        int d = 1 << (i % 10);
        layer_kernel<<<grid, 256>>>(Wd, bd, Wa, Ws, bs, Wr, br,
                                    hin, hout, cup, skip, i, d);
        float* tmp = hin; hin = hout; hout = tmp;
    }

    // head
    {
        int N = NB * TLEN;
        final_kernel<<<(N + 255) / 256, 256>>>(skip, Wl1, bl1, Wl2, bl2, out);
    }
}

// round 4
// speedup vs baseline: 2.9182x; 2.9161x over previous
#include <cuda_runtime.h>
#include <cuda_bf16.h>
#include <math.h>
#include <stdint.h>

#define TLEN 32768
#define NB 2
#define RC 64
#define GC 128
#define SC 64
#define AC 80
#define NLAYERS 30
#define SQRT_HALF 0.70710678118654752440f
#define SQRT_INV_L 0.18257418583505537115f

// ======================= scratch (device globals) ============================
__device__ float g_cup [NB * AC * TLEN];
__device__ float g_tmpA[NB * AC * 8192];
__device__ float g_tmpB[NB * AC * 8192];

__device__ __align__(16) __nv_bfloat16 g_hHa[NB * TLEN * RC];
__device__ __align__(16) __nv_bfloat16 g_hLa[NB * TLEN * RC];
__device__ __align__(16) __nv_bfloat16 g_hHb[NB * TLEN * RC];
__device__ __align__(16) __nv_bfloat16 g_hLb[NB * TLEN * RC];
__device__ float g_skip[NB * TLEN * SC];
__device__ __align__(16) __nv_bfloat16 g_cPH[NB * 2 * TLEN * 64];
__device__ __align__(16) __nv_bfloat16 g_cPL[NB * 2 * TLEN * 64];
__device__ __align__(16) __nv_bfloat16 g_WgH[NLAYERS * 5 * 128 * 64];
__device__ __align__(16) __nv_bfloat16 g_WgL[NLAYERS * 5 * 128 * 64];
__device__ __align__(16) __nv_bfloat16 g_W2H[NLAYERS * 128 * 64];
__device__ __align__(16) __nv_bfloat16 g_W2L[NLAYERS * 128 * 64];

// ======================= warp-mma helpers ====================================
__device__ __forceinline__ uint32_t smem_u32(const void* p) {
    uint32_t a;
    asm("{ .reg .u64 t; cvta.to.shared.u64 t, %1; cvt.u32.u64 %0, t; }" : "=r"(a) : "l"(p));
    return a;
}

__device__ __forceinline__ void ldm4(uint32_t* r, uint32_t addr) {
    asm volatile("ldmatrix.sync.aligned.m8n8.x4.shared.b16 {%0,%1,%2,%3}, [%4];"
        : "=r"(r[0]), "=r"(r[1]), "=r"(r[2]), "=r"(r[3]) : "r"(addr));
}

__device__ __forceinline__ void mma16816(float* d, const uint32_t* a, uint32_t b0, uint32_t b1) {
    asm volatile("mma.sync.aligned.m16n8k16.row.col.f32.bf16.bf16.f32 "
        "{%0,%1,%2,%3}, {%4,%5,%6,%7}, {%8,%9}, {%0,%1,%2,%3};"
        : "+f"(d[0]), "+f"(d[1]), "+f"(d[2]), "+f"(d[3])
        : "r"(a[0]), "r"(a[1]), "r"(a[2]), "r"(a[3]), "r"(b0), "r"(b1));
}

// ======================= conditioning / upsample =============================
__global__ void cin_kernel(const float* __restrict__ c, const float* __restrict__ Wc,
                           float* __restrict__ out) {
    int idx = blockIdx.x * blockDim.x + threadIdx.x;
    if (idx >= NB * AC * 128) return;
    int f = idx & 127;
    int o = (idx >> 7) % AC;
    int b = idx / (128 * AC);
    const float* cb = c + b * AC * 128;
    float acc = 0.f;
    #pragma unroll 4
    for (int i = 0; i < AC; ++i) acc += Wc[o * AC + i] * cb[i * 128 + f];
    out[idx] = acc;
}

__global__ void up_kernel(const float* __restrict__ in, float* __restrict__ out,
                          int Lin, const float* __restrict__ w9) {
    int Lout = Lin * 4;
    int N = NB * AC * Lout;
    int idx = blockIdx.x * blockDim.x + threadIdx.x;
    if (idx >= N) return;
    int t = idx % Lout;
    int bc = idx / Lout;
    const float* inb = in + bc * Lin;
    float w[9];
    #pragma unroll
    for (int k = 0; k < 9; ++k) w[k] = w9[k];
    float acc = 0.f;
    #pragma unroll
    for (int k = 0; k < 9; ++k) {
        int j = t - 4 + k;
        if (j >= 0 && j < Lout) acc += w[k] * inb[j >> 2];
    }
    out[idx] = acc;
}

// cup fp32 [b][80][t] -> bf16 hi/lo [b][cc][t][64]
__global__ void cup_pack(const float* __restrict__ cup,
                         __nv_bfloat16* __restrict__ PH, __nv_bfloat16* __restrict__ PL) {
    int idx = blockIdx.x * blockDim.x + threadIdx.x;
    if (idx >= NB * 2 * TLEN * 64) return;
    int j  = idx & 63;
    int t  = (idx >> 6) & (TLEN - 1);
    int cc = (idx >> 21) & 1;
    int b  = idx >> 22;
    float v = 0.f;
    if (cc == 0)          v = cup[((size_t)b * AC + j) * TLEN + t];
    else if (j < AC - 64) v = cup[((size_t)b * AC + 64 + j) * TLEN + t];
    __nv_bfloat16 h = __float2bfloat16(v);
    PH[idx] = h;
    PL[idx] = __float2bfloat16(v - __bfloat162float(h));
}

// weight prepack: GEMM1 row perm(r)=(r>>1)+((r&1)<<6); chunks: taps 0..2, cond lo/hi
__global__ void prepack_w(const float* __restrict__ Wd, const float* __restrict__ Wa,
                          const float* __restrict__ Ws, const float* __restrict__ Wr,
                          __nv_bfloat16* __restrict__ WgH, __nv_bfloat16* __restrict__ WgL,
                          __nv_bfloat16* __restrict__ W2H, __nv_bfloat16* __restrict__ W2L) {
    const int N1 = NLAYERS * 5 * 128 * 64;
    const int N2 = NLAYERS * 128 * 64;
    int i = blockIdx.x * blockDim.x + threadIdx.x;
    if (i < N1) {
        int kl = i & 63;
        int r  = (i >> 6) & 127;
        int lc = i >> 13;
        int c  = lc % 5;
        int l  = lc / 5;
        int ch = (r >> 1) + ((r & 1) << 6);
        float w;
        if (c < 3)       w = Wd[(((size_t)l * GC + ch) * RC + kl) * 3 + c];
        else if (c == 3) w = Wa[((size_t)l * GC + ch) * AC + kl];
        else             w = (kl < AC - 64) ? Wa[((size_t)l * GC + ch) * AC + 64 + kl] : 0.f;
        __nv_bfloat16 h = __float2bfloat16(w);
        WgH[i] = h;
        WgL[i] = __float2bfloat16(w - __bfloat162float(h));
    } else if (i - N1 < N2) {
        int i2 = i - N1;
        int k  = i2 & 63;
        int r2 = (i2 >> 6) & 127;
        int l  = i2 >> 13;
        float w = (r2 < 64) ? Ws[((size_t)l * SC + r2) * 64 + k]
                            : Wr[((size_t)l * RC + (r2 - 64)) * 64 + k];
        __nv_bfloat16 h = __float2bfloat16(w);
        W2H[i2] = h;
        W2L[i2] = __float2bfloat16(w - __bfloat162float(h));
    }
}

__global__ void first_pack(const float* __restrict__ x,
                           const float* __restrict__ Wf, const float* __restrict__ bf,
                           __nv_bfloat16* __restrict__ hH, __nv_bfloat16* __restrict__ hL,
                           float* __restrict__ skip) {
    int idx = blockIdx.x * blockDim.x + threadIdx.x;
    if (idx >= NB * TLEN * RC) return;
    int j = idx & 63;
    int t = (idx >> 6) & (TLEN - 1);
    int b = idx >> 21;
    float v = Wf[j] * x[(size_t)b * TLEN + t] + bf[j];
    __nv_bfloat16 h = __float2bfloat16(v);
    hH[idx] = h;
    hL[idx] = __float2bfloat16(v - __bfloat162float(h));
    skip[idx] = 0.f;
}

// ======================= fused residual layer (mma.sync bf16) ================
// smem: 4 regions of 128 rows x 144B (64 bf16 + pad). A=weights/z, B=data/W2.
#define STRIDE 144
#define OFF_A   0
#define OFF_AL  (128 * STRIDE)
#define OFF_B   (2 * 128 * STRIDE)
#define OFF_BL  (3 * 128 * STRIDE)
#define SMEM_NEED (4 * 128 * STRIDE)

__global__ __launch_bounds__(256)
void layer_mma(int l, int dil,
               const __nv_bfloat16* __restrict__ hinH, const __nv_bfloat16* __restrict__ hinL,
               __nv_bfloat16* __restrict__ houtH, __nv_bfloat16* __restrict__ houtL,
               const __nv_bfloat16* __restrict__ cPH, const __nv_bfloat16* __restrict__ cPL,
               float* __restrict__ skip,
               const __nv_bfloat16* __restrict__ WgH, const __nv_bfloat16* __restrict__ WgL,
               const __nv_bfloat16* __restrict__ W2H, const __nv_bfloat16* __restrict__ W2L,
               const float* __restrict__ bd, const float* __restrict__ bs,
               const float* __restrict__ br) {
    extern __shared__ char smem_c[];
    const uint32_t sb = smem_u32(smem_c);

    const int tid   = threadIdx.x;          // 256 threads, 8 warps
    const int warp  = tid >> 5;
    const int lane  = tid & 31;
    const int b     = blockIdx.y;
    const int t0    = blockIdx.x * 128;
    const int mbase = warp * 16;

    // ldmatrix per-lane addressing pieces
    const int lrow  = lane & 15;            // row within 16-row group
    const int lkoff = (lane >> 4) * 16;     // byte offset for k-block (8 bf16)
    const uint32_t a_lane = sb + (uint32_t)(mbase + lrow) * STRIDE + lkoff;

    float acc[16][4];
    #pragma unroll
    for (int i = 0; i < 16; ++i)
        #pragma unroll
        for (int j = 0; j < 4; ++j) acc[i][j] = 0.f;

    // ---------------- GEMM1: K chunks (3 taps + 2 cond) ----------------
    for (int c = 0; c < 5; ++c) {
        const uint4* aH = (const uint4*)(WgH + (((size_t)l * 5 + c) * 128) * 64);
        const uint4* aL = (const uint4*)(WgL + (((size_t)l * 5 + c) * 128) * 64);
        for (int p = tid; p < 1024; p += 256) {
            int row = p >> 3, j = p & 7;
            if (c == 4 && j >= 2) continue;          // only 16 real k in chunk 4
            uint32_t d = (uint32_t)row * STRIDE + j * 16;
            *(uint4*)(smem_c + OFF_A  + d) = aH[p];
            *(uint4*)(smem_c + OFF_AL + d) = aL[p];
            uint4 vh = make_uint4(0, 0, 0, 0), vl = make_uint4(0, 0, 0, 0);
            if (c < 3) {
                int tg = t0 + row + (c - 1) * dil;
                if (tg >= 0 && tg < TLEN) {
                    size_t base = ((size_t)b * TLEN + tg) * 8 + j;
                    vh = ((const uint4*)hinH)[base];
                    vl = ((const uint4*)hinL)[base];
                }
            } else {
                size_t base = (((size_t)b * 2 + (c - 3)) * TLEN + (t0 + row)) * 8 + j;
                vh = ((const uint4*)cPH)[base];
                vl = ((const uint4*)cPL)[base];
            }
            *(uint4*)(smem_c + OFF_B  + d) = vh;
            *(uint4*)(smem_c + OFF_BL + d) = vl;
        }
        __syncthreads();
        const int nks = (c == 4) ? 1 : 4;
        for (int ks = 0; ks < nks; ++ks) {
            uint32_t ah[4], al[4];
            ldm4(ah, a_lane + OFF_A  + ks * 32);
            ldm4(al, a_lane + OFF_AL + ks * 32);
            #pragma unroll
            for (int nt = 0; nt < 8; ++nt) {
                uint32_t bh[4], bl[4];
                uint32_t baddr = sb + (uint32_t)(nt * 16 + lrow) * STRIDE + lkoff + ks * 32;
                ldm4(bh, baddr + OFF_B);
                ldm4(bl, baddr + OFF_BL);
                mma16816(acc[nt * 2],     ah, bh[0], bh[2]);
                mma16816(acc[nt * 2 + 1], ah, bh[1], bh[3]);
                mma16816(acc[nt * 2],     ah, bl[0], bl[2]);
                mma16816(acc[nt * 2 + 1], ah, bl[1], bl[3]);
                mma16816(acc[nt * 2],     al, bh[0], bh[2]);
                mma16816(acc[nt * 2 + 1], al, bh[1], bh[3]);
            }
        }
        __syncthreads();
    }

    // ---------------- stage GEMM2 weights into B region ----------------
    {
        const uint4* wH = (const uint4*)(W2H + (size_t)l * 128 * 64);
        const uint4* wL = (const uint4*)(W2L + (size_t)l * 128 * 64);
        for (int p = tid; p < 1024; p += 256) {
            int row = p >> 3, j = p & 7;
            uint32_t d = (uint32_t)row * STRIDE + j * 16;
            *(uint4*)(smem_c + OFF_B  + d) = wH[p];
            *(uint4*)(smem_c + OFF_BL + d) = wL[p];
        }
    }

    // ---------------- gate: z = tanh(xa)*sigmoid(xb) -> A region ----------
    {
        const int r0 = mbase + (lane >> 2);
        const int r1 = r0 + 8;
        const float bias0 = bd[l * GC + ((r0 >> 1) + ((r0 & 1) << 6))];
        const float bias1 = bd[l * GC + ((r1 >> 1) + ((r1 & 1) << 6))];
        const bool evenrow = ((lane & 4) == 0);
        const int j0 = r0 >> 1, j1 = r1 >> 1;
        #pragma unroll
        for (int a = 0; a < 16; ++a) {
            const int tb = (a >> 1) * 16 + (a & 1) * 8 + 2 * (lane & 3);
            float v[4];
            v[0] = acc[a][0] + bias0;
            v[1] = acc[a][1] + bias0;
            v[2] = acc[a][2] + bias1;
            v[3] = acc[a][3] + bias1;
            float p0 = __shfl_xor_sync(0xffffffffu, v[0], 4);
            float p1 = __shfl_xor_sync(0xffffffffu, v[1], 4);
            float p2 = __shfl_xor_sync(0xffffffffu, v[2], 4);
            float p3 = __shfl_xor_sync(0xffffffffu, v[3], 4);
            if (evenrow) {
                float xa[4] = {v[0], v[1], v[2], v[3]};
                float xb[4] = {p0, p1, p2, p3};
                #pragma unroll
                for (int i = 0; i < 4; ++i) {
                    float e2 = __expf(-2.f * fabsf(xa[i]));
                    float th = copysignf(__fdividef(1.f - e2, 1.f + e2), xa[i]);
                    float sg = __fdividef(1.f, 1.f + __expf(-xb[i]));
                    float z = th * sg;
                    int t = tb + (i & 1);
                    int j = (i < 2) ? j0 : j1;
                    uint32_t d = (uint32_t)t * STRIDE + j * 2;
                    __nv_bfloat16 zh = __float2bfloat16(z);
                    *(__nv_bfloat16*)(smem_c + OFF_A  + d) = zh;
                    *(__nv_bfloat16*)(smem_c + OFF_AL + d) =
                        __float2bfloat16(z - __bfloat162float(zh));
                }
            }
        }
    }
    __syncthreads();

    // ---------------- GEMM2: [Ws;Wr](128x64) x z ----------------
    #pragma unroll
    for (int i = 0; i < 16; ++i)
        #pragma unroll
        for (int j = 0; j < 4; ++j) acc[i][j] = 0.f;

    for (int ks = 0; ks < 4; ++ks) {
        uint32_t ah[4], al[4];
        ldm4(ah, a_lane + OFF_B  + ks * 32);   // W2 hi
        ldm4(al, a_lane + OFF_BL + ks * 32);   // W2 lo
        #pragma unroll
        for (int nt = 0; nt < 8; ++nt) {
            uint32_t bh[4], bl[4];
            uint32_t baddr = sb + (uint32_t)(nt * 16 + lrow) * STRIDE + lkoff + ks * 32;
            ldm4(bh, baddr + OFF_A);           // z hi
            ldm4(bl, baddr + OFF_AL);          // z lo
            mma16816(acc[nt * 2],     ah, bh[0], bh[2]);
            mma16816(acc[nt * 2 + 1], ah, bh[1], bh[3]);
            mma16816(acc[nt * 2],     ah, bl[0], bl[2]);
            mma16816(acc[nt * 2 + 1], ah, bl[1], bl[3]);
            mma16816(acc[nt * 2],     al, bh[0], bh[2]);
            mma16816(acc[nt * 2 + 1], al, bh[1], bh[3]);
        }
    }

    // ---------------- epilogue ----------------
    {
        const int r0 = mbase + (lane >> 2);
        const int r1 = r0 + 8;
        if (mbase < 64) {                      // skip channels
            const float bs0 = bs[l * SC + r0];
            const float bs1 = bs[l * SC + r1];
            #pragma unroll
            for (int a = 0; a < 16; ++a) {
                const int tb = (a >> 1) * 16 + (a & 1) * 8 + 2 * (lane & 3);
                #pragma unroll
                for (int i = 0; i < 4; ++i) {
                    int t = t0 + tb + (i & 1);
                    int ch = (i < 2) ? r0 : r1;
                    float bsv = (i < 2) ? bs0 : bs1;
                    size_t off = ((size_t)b * TLEN + t) * 64 + ch;
                    skip[off] += acc[a][i] + bsv;
                }
            }
        } else {                               // residual channels
            const int c0 = r0 - 64, c1 = r1 - 64;
            const float br0 = br[l * RC + c0];
            const float br1 = br[l * RC + c1];
            #pragma unroll
            for (int a = 0; a < 16; ++a) {
                const int tb = (a >> 1) * 16 + (a & 1) * 8 + 2 * (lane & 3);
                #pragma unroll
                for (int i = 0; i < 4; ++i) {
                    int t = t0 + tb + (i & 1);
                    int ch = (i < 2) ? c0 : c1;
                    float brv = (i < 2) ? br0 : br1;
                    size_t off = ((size_t)b * TLEN + t) * 64 + ch;
                    float hin = __bfloat162float(hinH[off]) + __bfloat162float(hinL[off]);
                    float hv = (acc[a][i] + brv + hin) * SQRT_HALF;
                    __nv_bfloat16 hh = __float2bfloat16(hv);
                    houtH[off] = hh;
                    houtL[off] = __float2bfloat16(hv - __bfloat162float(hh));
                }
            }
        }
    }
}

// ======================= final head ==========================================
__global__ void final2(const float* __restrict__ skip,
                       const float* __restrict__ Wl1, const float* __restrict__ bl1,
                       const float* __restrict__ Wl2, const float* __restrict__ bl2,
                       float* __restrict__ out) {
    __shared__ float tile[128 * 65];
    __shared__ float b1s[64];
    __shared__ float W2s[64];
    int tid = threadIdx.x;   // 128
    if (tid < 64) { b1s[tid] = bl1[tid]; W2s[tid] = Wl2[tid]; }
    int t0 = (blockIdx.x & 255) * 128;
    int b  = blockIdx.x >> 8;
    for (int i = tid; i < 128 * 64; i += 128) {
        int r = i >> 6, cc = i & 63;
        tile[r * 65 + cc] = skip[((size_t)b * TLEN + t0) * 64 + i];
    }
    __syncthreads();
    float s1[64];
    #pragma unroll 8
    for (int j = 0; j < 64; ++j)
        s1[j] = fmaxf(tile[tid * 65 + j] * SQRT_INV_L, 0.f);
    float y2 = bl2[0];
    for (int o = 0; o < 64; ++o) {
        float a = b1s[o];
        #pragma unroll 8
        for (int j = 0; j < 64; ++j) a += Wl1[o * 64 + j] * s1[j];
        y2 += W2s[o] * fmaxf(a, 0.f);
    }
    out[(size_t)b * TLEN + t0 + tid] = y2;
}

// ======================= launch ==============================================
extern "C" void kernel_launch(void* const* d_in, const int* in_sizes, int n_in,
                              void* d_out, int out_size)
{
    const float* x       = (const float*)d_in[0];
    const float* c       = (const float*)d_in[1];
    const float* W_first = (const float*)d_in[2];
    const float* b_first = (const float*)d_in[3];
    const float* W_cin   = (const float*)d_in[4];
    const float* W_up    = (const float*)d_in[5];
    const float* Wd      = (const float*)d_in[6];
    const float* bd      = (const float*)d_in[7];
    const float* Wa      = (const float*)d_in[8];
    const float* Ws      = (const float*)d_in[9];
    const float* bs      = (const float*)d_in[10];
    const float* Wr      = (const float*)d_in[11];
    const float* br      = (const float*)d_in[12];
    const float* Wl1     = (const float*)d_in[13];
    const float* bl1     = (const float*)d_in[14];
    const float* Wl2     = (const float*)d_in[15];
    const float* bl2     = (const float*)d_in[16];
    float* out = (float*)d_out;

    float *cup, *tA, *tB, *skip;
    __nv_bfloat16 *hHa, *hLa, *hHb, *hLb, *cPH, *cPL, *WgH, *WgL, *W2H, *W2L;
    cudaGetSymbolAddress((void**)&cup,  g_cup);
    cudaGetSymbolAddress((void**)&tA,   g_tmpA);
    cudaGetSymbolAddress((void**)&tB,   g_tmpB);
    cudaGetSymbolAddress((void**)&skip, g_skip);
    cudaGetSymbolAddress((void**)&hHa,  g_hHa);
    cudaGetSymbolAddress((void**)&hLa,  g_hLa);
    cudaGetSymbolAddress((void**)&hHb,  g_hHb);
    cudaGetSymbolAddress((void**)&hLb,  g_hLb);
    cudaGetSymbolAddress((void**)&cPH,  g_cPH);
    cudaGetSymbolAddress((void**)&cPL,  g_cPL);
    cudaGetSymbolAddress((void**)&WgH,  g_WgH);
    cudaGetSymbolAddress((void**)&WgL,  g_WgL);
    cudaGetSymbolAddress((void**)&W2H,  g_W2H);
    cudaGetSymbolAddress((void**)&W2L,  g_W2L);

    cudaFuncSetAttribute(layer_mma, cudaFuncAttributeMaxDynamicSharedMemorySize, SMEM_NEED);

    // conditioning pipeline
    { int N = NB * AC * 128;  cin_kernel<<<(N + 255) / 256, 256>>>(c, W_cin, tA); }
    { int Lin = 128,  N = NB * AC * Lin * 4; up_kernel<<<(N + 255) / 256, 256>>>(tA, tB, Lin, W_up + 0); }
    { int Lin = 512,  N = NB * AC * Lin * 4; up_kernel<<<(N + 255) / 256, 256>>>(tB, tA, Lin, W_up + 9); }
    { int Lin = 2048, N = NB * AC * Lin * 4; up_kernel<<<(N + 255) / 256, 256>>>(tA, tB, Lin, W_up + 18); }
    { int Lin = 8192, N = NB * AC * Lin * 4; up_kernel<<<(N + 255) / 256, 256>>>(tB, cup, Lin, W_up + 27); }
    { int N = NB * 2 * TLEN * 64; cup_pack<<<(N + 255) / 256, 256>>>(cup, cPH, cPL); }
    { int N = NLAYERS * 5 * 128 * 64 + NLAYERS * 128 * 64;
      prepack_w<<<(N + 255) / 256, 256>>>(Wd, Wa, Ws, Wr, WgH, WgL, W2H, W2L); }
    { int N = NB * TLEN * RC;
      first_pack<<<(N + 255) / 256, 256>>>(x, W_first, b_first, hHa, hLa, skip); }

    // 30 residual layers (ping-pong)
    __nv_bfloat16 *hiH = hHa, *hiL = hLa, *hoH = hHb, *hoL = hLb;
    dim3 grid(TLEN / 128, NB);
    for (int i = 0; i < NLAYERS; ++i) {
        int d = 1 << (i % 10);
        layer_mma<<<grid, 256, SMEM_NEED>>>(i, d, hiH, hiL, hoH, hoL,
                                            cPH, cPL, skip, WgH, WgL, W2H, W2L, bd, bs, br);
        { __nv_bfloat16* t = hiH; hiH = hoH; hoH = t; }
        { __nv_bfloat16* t = hiL; hiL = hoL; hoL = t; }
    }

    final2<<<NB * (TLEN / 128), 128>>>(skip, Wl1, bl1, Wl2, bl2, out);
}

// round 5
// speedup vs baseline: 3.9346x; 1.3483x over previous
#include <cuda_runtime.h>
#include <cuda_bf16.h>
#include <math.h>
#include <stdint.h>

#define TLEN 32768
#define NB 2
#define RC 64
#define GC 128
#define SC 64
#define AC 80
#define NLAYERS 30
#define SQRT_HALF 0.70710678118654752440f
#define SQRT_INV_L 0.18257418583505537115f

// ======================= scratch (device globals) ============================
__device__ __align__(16) __nv_bfloat16 g_hHa[NB * TLEN * RC];
__device__ __align__(16) __nv_bfloat16 g_hLa[NB * TLEN * RC];
__device__ __align__(16) __nv_bfloat16 g_hHb[NB * TLEN * RC];
__device__ __align__(16) __nv_bfloat16 g_hLb[NB * TLEN * RC];
__device__ float g_skip[NB * TLEN * SC];
__device__ __align__(16) __nv_bfloat16 g_cPH[NB * 2 * TLEN * 64];
__device__ __align__(16) __nv_bfloat16 g_cPL[NB * 2 * TLEN * 64];
__device__ __align__(16) __nv_bfloat16 g_WgH[NLAYERS * 5 * 128 * 64];
__device__ __align__(16) __nv_bfloat16 g_WgL[NLAYERS * 5 * 128 * 64];
__device__ __align__(16) __nv_bfloat16 g_W2H[NLAYERS * 128 * 64];
__device__ __align__(16) __nv_bfloat16 g_W2L[NLAYERS * 128 * 64];

// ======================= helpers =============================================
__device__ __forceinline__ uint32_t smem_u32(const void* p) {
    uint32_t a;
    asm("{ .reg .u64 t; cvta.to.shared.u64 t, %1; cvt.u32.u64 %0, t; }" : "=r"(a) : "l"(p));
    return a;
}
__device__ __forceinline__ void ldm4(uint32_t* r, uint32_t addr) {
    asm volatile("ldmatrix.sync.aligned.m8n8.x4.shared.b16 {%0,%1,%2,%3}, [%4];"
        : "=r"(r[0]), "=r"(r[1]), "=r"(r[2]), "=r"(r[3]) : "r"(addr));
}
__device__ __forceinline__ void mma16816(float* d, const uint32_t* a, uint32_t b0, uint32_t b1) {
    asm volatile("mma.sync.aligned.m16n8k16.row.col.f32.bf16.bf16.f32 "
        "{%0,%1,%2,%3}, {%4,%5,%6,%7}, {%8,%9}, {%0,%1,%2,%3};"
        : "+f"(d[0]), "+f"(d[1]), "+f"(d[2]), "+f"(d[3])
        : "r"(a[0]), "r"(a[1]), "r"(a[2]), "r"(a[3]), "r"(b0), "r"(b1));
}
__device__ __forceinline__ void cpa16(uint32_t dst, const void* src, int srcsz) {
    asm volatile("cp.async.ca.shared.global [%0], [%1], 16, %2;"
        :: "r"(dst), "l"(src), "r"(srcsz) : "memory");
}
#define CP_COMMIT() asm volatile("cp.async.commit_group;" ::: "memory")
#define CP_WAIT0()  asm volatile("cp.async.wait_group 0;" ::: "memory")

__device__ __forceinline__ uint32_t packbf2(float lo, float hi) {
    __nv_bfloat162 t = __floats2bfloat162_rn(lo, hi);
    return *(uint32_t*)&t;
}

// ======================= fused conditioning ==================================
// one kernel: 1x1 cin -> 4x (repeat x4 + 9-tap conv) -> bf16 hi/lo pack
__global__ void cond_fused(const float* __restrict__ c, const float* __restrict__ Wc,
                           const float* __restrict__ Wup,
                           __nv_bfloat16* __restrict__ PH, __nv_bfloat16* __restrict__ PL) {
    extern __shared__ float us[];
    const int b  = blockIdx.y;
    const int t0 = blockIdx.x * 128;
    const int tid = threadIdx.x;   // 256

    const int u0 = (t0 - 4) >> 2;
    const int un = ((t0 + 131) >> 2) - u0 + 1;          // <= 35
    const int v0 = (u0 - 4) >> 2;
    const int vn = ((u0 + un - 1 + 4) >> 2) - v0 + 1;   // <= 13
    const int w0 = (v0 - 4) >> 2;
    const int wn = ((v0 + vn - 1 + 4) >> 2) - w0 + 1;   // <= 7
    const int f0 = (w0 - 4) >> 2;
    const int fn = ((w0 + wn - 1 + 4) >> 2) - f0 + 1;   // <= 5

    float* y0 = us;                 // [80][6]
    float* y1 = y0 + 80 * 6;        // [80][8]
    float* s1 = y1 + 80 * 8;        // [80][8]
    float* s2 = s1 + 80 * 8;        // [80][14]
    float* s3 = s2 + 80 * 14;       // [80][36]
    float* s4 = s3 + 80 * 36;       // [80][128]

    // P0: raw frames
    for (int i = tid; i < 80 * fn; i += 256) {
        int ch = i / fn, ff = i - ch * fn;
        int f = f0 + ff;
        y0[ch * 6 + ff] = (f >= 0 && f < 128) ? c[((size_t)b * 80 + ch) * 128 + f] : 0.f;
    }
    __syncthreads();
    // P1: 1x1 conv
    for (int i = tid; i < 80 * fn; i += 256) {
        int o = i / fn, ff = i - o * fn;
        float acc = 0.f;
        #pragma unroll 4
        for (int k = 0; k < 80; ++k) acc += Wc[o * 80 + k] * y0[k * 6 + ff];
        y1[o * 8 + ff] = acc;
    }
    __syncthreads();
    // P2: stage 1 (len 512)
    for (int i = tid; i < 80 * wn; i += 256) {
        int o = i / wn, wi = i - o * wn;
        int w = w0 + wi;
        float acc = 0.f;
        #pragma unroll
        for (int k = 0; k < 9; ++k) {
            int rr = w - 4 + k;
            if (rr >= 0 && rr < 512) acc += Wup[k] * y1[o * 8 + ((rr >> 2) - f0)];
        }
        s1[o * 8 + wi] = acc;
    }
    __syncthreads();
    // P3: stage 2 (len 2048)
    for (int i = tid; i < 80 * vn; i += 256) {
        int o = i / vn, vi = i - o * vn;
        int v = v0 + vi;
        float acc = 0.f;
        #pragma unroll
        for (int k = 0; k < 9; ++k) {
            int rr = v - 4 + k;
            if (rr >= 0 && rr < 2048) acc += Wup[9 + k] * s1[o * 8 + ((rr >> 2) - w0)];
        }
        s2[o * 14 + vi] = acc;
    }
    __syncthreads();
    // P4: stage 3 (len 8192)
    for (int i = tid; i < 80 * un; i += 256) {
        int o = i / un, ui = i - o * un;
        int u = u0 + ui;
        float acc = 0.f;
        #pragma unroll
        for (int k = 0; k < 9; ++k) {
            int rr = u - 4 + k;
            if (rr >= 0 && rr < 8192) acc += Wup[18 + k] * s2[o * 14 + ((rr >> 2) - v0)];
        }
        s3[o * 36 + ui] = acc;
    }
    __syncthreads();
    // P5: stage 4 (len 32768)
    for (int i = tid; i < 80 * 128; i += 256) {
        int o = i >> 7, tl = i & 127;
        int t = t0 + tl;
        float acc = 0.f;
        #pragma unroll
        for (int k = 0; k < 9; ++k) {
            int rr = t - 4 + k;
            if (rr >= 0 && rr < TLEN) acc += Wup[27 + k] * s3[o * 36 + ((rr >> 2) - u0)];
        }
        s4[o * 128 + tl] = acc;
    }
    __syncthreads();
    // P6: transpose + bf16 hi/lo pack  (cc=0: ch0-63, cc=1: ch64-79 + zeros)
    for (int i = tid; i < 128 * 64; i += 256) {
        int tl = i >> 6, j = i & 63;
        size_t o0 = (((size_t)b * 2 + 0) * TLEN + (t0 + tl)) * 64 + j;
        size_t o1 = (((size_t)b * 2 + 1) * TLEN + (t0 + tl)) * 64 + j;
        float v0f = s4[j * 128 + tl];
        float v1f = (j < 16) ? s4[(64 + j) * 128 + tl] : 0.f;
        __nv_bfloat16 h0 = __float2bfloat16(v0f);
        __nv_bfloat16 h1 = __float2bfloat16(v1f);
        PH[o0] = h0;  PL[o0] = __float2bfloat16(v0f - __bfloat162float(h0));
        PH[o1] = h1;  PL[o1] = __float2bfloat16(v1f - __bfloat162float(h1));
    }
}

// ======================= weight prepack ======================================
// GEMM1 col perm: col r -> j = 8*(r>>4) + 2*((r&7)>>1) + ((r>>3)&1); ab = r&1
__global__ void prepack_w(const float* __restrict__ Wd, const float* __restrict__ Wa,
                          const float* __restrict__ Ws, const float* __restrict__ Wr,
                          __nv_bfloat16* __restrict__ WgH, __nv_bfloat16* __restrict__ WgL,
                          __nv_bfloat16* __restrict__ W2H, __nv_bfloat16* __restrict__ W2L) {
    const int N1 = NLAYERS * 5 * 128 * 64;
    const int N2 = NLAYERS * 128 * 64;
    int i = blockIdx.x * blockDim.x + threadIdx.x;
    if (i < N1) {
        int kl = i & 63;
        int r  = (i >> 6) & 127;
        int lc = i >> 13;
        int cc = lc % 5;
        int l  = lc / 5;
        int j  = ((r >> 4) << 3) + (((r & 7) >> 1) << 1) + ((r >> 3) & 1);
        int ch = (r & 1) ? (64 + j) : j;
        float w;
        if (cc < 3)       w = Wd[(((size_t)l * GC + ch) * RC + kl) * 3 + cc];
        else if (cc == 3) w = Wa[((size_t)l * GC + ch) * AC + kl];
        else              w = (kl < AC - 64) ? Wa[((size_t)l * GC + ch) * AC + 64 + kl] : 0.f;
        __nv_bfloat16 h = __float2bfloat16(w);
        WgH[i] = h;
        WgL[i] = __float2bfloat16(w - __bfloat162float(h));
    } else if (i - N1 < N2) {
        int i2 = i - N1;
        int k  = i2 & 63;
        int r2 = (i2 >> 6) & 127;
        int l  = i2 >> 13;
        float w = (r2 < 64) ? Ws[((size_t)l * SC + r2) * 64 + k]
                            : Wr[((size_t)l * RC + (r2 - 64)) * 64 + k];
        __nv_bfloat16 h = __float2bfloat16(w);
        W2H[i2] = h;
        W2L[i2] = __float2bfloat16(w - __bfloat162float(h));
    }
}

__global__ void first_pack(const float* __restrict__ x,
                           const float* __restrict__ Wf, const float* __restrict__ bf,
                           __nv_bfloat16* __restrict__ hH, __nv_bfloat16* __restrict__ hL,
                           float* __restrict__ skip) {
    int idx = blockIdx.x * blockDim.x + threadIdx.x;
    if (idx >= NB * TLEN * RC) return;
    int j = idx & 63;
    int t = (idx >> 6) & (TLEN - 1);
    int b = idx >> 21;
    float v = Wf[j] * x[(size_t)b * TLEN + t] + bf[j];
    __nv_bfloat16 h = __float2bfloat16(v);
    hH[idx] = h;
    hL[idx] = __float2bfloat16(v - __bfloat162float(h));
    skip[idx] = 0.f;
}

// ======================= fused residual layer ================================
#define STRIDE 144
#define OFF_WH  0
#define OFF_WL  (128 * STRIDE)
#define OFF_DH  (2 * 128 * STRIDE)
#define OFF_DL  (3 * 128 * STRIDE)
#define OFF_BD  (4 * 128 * STRIDE)
#define SMEM_NEED (OFF_BD + 512)

__global__ __launch_bounds__(256, 2)
void layer_mma(int l, int dil,
               const __nv_bfloat16* __restrict__ hinH, const __nv_bfloat16* __restrict__ hinL,
               __nv_bfloat16* __restrict__ houtH, __nv_bfloat16* __restrict__ houtL,
               const __nv_bfloat16* __restrict__ cPH, const __nv_bfloat16* __restrict__ cPL,
               float* __restrict__ skip,
               const __nv_bfloat16* __restrict__ WgH, const __nv_bfloat16* __restrict__ WgL,
               const __nv_bfloat16* __restrict__ W2H, const __nv_bfloat16* __restrict__ W2L,
               const float* __restrict__ bd, const float* __restrict__ bs,
               const float* __restrict__ br) {
    extern __shared__ char smem_c[];
    const uint32_t sb = smem_u32(smem_c);
    float* sbd = (float*)(smem_c + OFF_BD);

    const int tid  = threadIdx.x;
    const int warp = tid >> 5;
    const int lane = tid & 31;
    const int b    = blockIdx.y;
    const int t0   = blockIdx.x * 128;
    const int mbase = warp * 16;            // warp's 16 t-rows

    const int lrow  = lane & 15;
    const int lkoff = (lane >> 4) * 16;
    const int q     = lane & 3;
    const int r     = lane >> 2;

    if (tid < 128) sbd[tid] = bd[l * GC + tid];

    // ---- chunk staging via cp.async ----
    auto stage_chunk = [&](int c) {
        const char* wH = (const char*)(WgH + (((size_t)l * 5 + c) * 128) * 64);
        const char* wL = (const char*)(WgL + (((size_t)l * 5 + c) * 128) * 64);
        for (int p = tid; p < 1024; p += 256) {
            int row = p >> 3, j = p & 7;
            if (c == 4 && j >= 2) continue;
            uint32_t d = (uint32_t)row * STRIDE + j * 16;
            cpa16(sb + OFF_WH + d, wH + (size_t)p * 16, 16);
            cpa16(sb + OFF_WL + d, wL + (size_t)p * 16, 16);
            const char* srcH;
            const char* srcL;
            int sz = 16;
            if (c < 3) {
                int tg = t0 + row + (c - 1) * dil;
                if (tg >= 0 && tg < TLEN) {
                    size_t e = ((size_t)b * TLEN + tg) * 64 + j * 8;
                    srcH = (const char*)(hinH + e);
                    srcL = (const char*)(hinL + e);
                } else { srcH = (const char*)hinH; srcL = (const char*)hinL; sz = 0; }
            } else {
                size_t e = (((size_t)b * 2 + (c - 3)) * TLEN + (t0 + row)) * 64 + j * 8;
                srcH = (const char*)(cPH + e);
                srcL = (const char*)(cPL + e);
            }
            cpa16(sb + OFF_DH + d, srcH, sz);
            cpa16(sb + OFF_DL + d, srcL, sz);
        }
        CP_COMMIT();
    };

    stage_chunk(0);

    float acc[16][4];
    #pragma unroll
    for (int i = 0; i < 16; ++i)
        #pragma unroll
        for (int j2 = 0; j2 < 4; ++j2) acc[i][j2] = 0.f;

    // ---------------- GEMM1: D1[t][gch] ----------------
    for (int c = 0; c < 5; ++c) {
        CP_WAIT0();
        __syncthreads();
        const int nks = (c == 4) ? 1 : 4;
        const uint32_t a_base = sb + (uint32_t)(mbase + lrow) * STRIDE + lkoff;
        for (int ks = 0; ks < nks; ++ks) {
            uint32_t ah[4], al[4];
            ldm4(ah, a_base + OFF_DH + ks * 32);
            ldm4(al, a_base + OFF_DL + ks * 32);
            #pragma unroll
            for (int nt = 0; nt < 8; ++nt) {
                uint32_t bh[4], bl[4];
                uint32_t baddr = sb + (uint32_t)(nt * 16 + lrow) * STRIDE + lkoff + ks * 32;
                ldm4(bh, baddr + OFF_WH);
                ldm4(bl, baddr + OFF_WL);
                mma16816(acc[nt * 2],     ah, bh[0], bh[2]);
                mma16816(acc[nt * 2 + 1], ah, bh[1], bh[3]);
                mma16816(acc[nt * 2],     ah, bl[0], bl[2]);
                mma16816(acc[nt * 2 + 1], ah, bl[1], bl[3]);
                mma16816(acc[nt * 2],     al, bh[0], bh[2]);
                mma16816(acc[nt * 2 + 1], al, bh[1], bh[3]);
            }
        }
        __syncthreads();
        if (c < 4) stage_chunk(c + 1);
    }

    // stage W2 (overlaps gate)
    {
        const char* wH = (const char*)(W2H + (size_t)l * 128 * 64);
        const char* wL = (const char*)(W2L + (size_t)l * 128 * 64);
        for (int p = tid; p < 1024; p += 256) {
            int row = p >> 3, j = p & 7;
            uint32_t d = (uint32_t)row * STRIDE + j * 16;
            cpa16(sb + OFF_WH + d, wH + (size_t)p * 16, 16);
            cpa16(sb + OFF_WL + d, wL + (size_t)p * 16, 16);
        }
        CP_COMMIT();
    }

    // ---------------- gate (registers only) ----------------
    uint32_t zhA[8], zlA[8], zhB[8], zlB[8];
    #pragma unroll
    for (int nt = 0; nt < 8; ++nt) {
        float zA[2], zB[2];
        #pragma unroll
        for (int s = 0; s < 2; ++s) {
            int j = nt * 8 + 2 * q + s;
            float ba = sbd[j], bb = sbd[64 + j];
            #pragma unroll
            for (int h = 0; h < 2; ++h) {
                float xa = acc[nt * 2 + s][h * 2 + 0] + ba;
                float xb = acc[nt * 2 + s][h * 2 + 1] + bb;
                float e2 = __expf(-2.f * fabsf(xa));
                float th = copysignf(__fdividef(1.f - e2, 1.f + e2), xa);
                float sg = __fdividef(1.f, 1.f + __expf(-xb));
                float z = th * sg;
                if (h == 0) zA[s] = z; else zB[s] = z;
            }
        }
        zhA[nt] = packbf2(zA[0], zA[1]);
        zhB[nt] = packbf2(zB[0], zB[1]);
        __nv_bfloat162 hA = *(__nv_bfloat162*)&zhA[nt];
        __nv_bfloat162 hB = *(__nv_bfloat162*)&zhB[nt];
        zlA[nt] = packbf2(zA[0] - __bfloat162float(hA.x), zA[1] - __bfloat162float(hA.y));
        zlB[nt] = packbf2(zB[0] - __bfloat162float(hB.x), zB[1] - __bfloat162float(hB.y));
    }

    CP_WAIT0();
    __syncthreads();

    // ---------------- GEMM2: D2[t][och] = z(t x 64) * W2^T ----------------
    float acc2[16][4];
    #pragma unroll
    for (int i = 0; i < 16; ++i)
        #pragma unroll
        for (int j2 = 0; j2 < 4; ++j2) acc2[i][j2] = 0.f;

    #pragma unroll
    for (int ks = 0; ks < 4; ++ks) {
        uint32_t azh[4] = {zhA[2 * ks], zhB[2 * ks], zhA[2 * ks + 1], zhB[2 * ks + 1]};
        uint32_t azl[4] = {zlA[2 * ks], zlB[2 * ks], zlA[2 * ks + 1], zlB[2 * ks + 1]};
        #pragma unroll
        for (int nt = 0; nt < 8; ++nt) {
            uint32_t wh[4], wl[4];
            uint32_t baddr = sb + (uint32_t)(nt * 16 + lrow) * STRIDE + lkoff + ks * 32;
            ldm4(wh, baddr + OFF_WH);
            ldm4(wl, baddr + OFF_WL);
            mma16816(acc2[nt * 2],     azh, wh[0], wh[2]);
            mma16816(acc2[nt * 2 + 1], azh, wh[1], wh[3]);
            mma16816(acc2[nt * 2],     azh, wl[0], wl[2]);
            mma16816(acc2[nt * 2 + 1], azh, wl[1], wl[3]);
            mma16816(acc2[nt * 2],     azl, wh[0], wh[2]);
            mma16816(acc2[nt * 2 + 1], azl, wh[1], wh[3]);
        }
    }

    // ---------------- epilogue (coalesced [t][ch]) ----------------
    const int trowA = t0 + mbase + r;
    const int trowB = trowA + 8;
    #pragma unroll
    for (int nt = 0; nt < 8; ++nt) {
        #pragma unroll
        for (int s = 0; s < 2; ++s) {
            int cch = nt * 16 + s * 8 + 2 * q;
            float d0 = acc2[nt * 2 + s][0], d1 = acc2[nt * 2 + s][1];
            float d2 = acc2[nt * 2 + s][2], d3 = acc2[nt * 2 + s][3];
            if (cch < 64) {
                float bs0 = bs[l * SC + cch], bs1 = bs[l * SC + cch + 1];
                float2* p1 = (float2*)&skip[((size_t)b * TLEN + trowA) * 64 + cch];
                float2* p2 = (float2*)&skip[((size_t)b * TLEN + trowB) * 64 + cch];
                float2 v1 = *p1, v2 = *p2;
                v1.x += d0 + bs0; v1.y += d1 + bs1;
                v2.x += d2 + bs0; v2.y += d3 + bs1;
                *p1 = v1; *p2 = v2;
            } else {
                int ch = cch - 64;
                float br0 = br[l * RC + ch], br1 = br[l * RC + ch + 1];
                size_t e1 = ((size_t)b * TLEN + trowA) * 64 + ch;
                size_t e2 = ((size_t)b * TLEN + trowB) * 64 + ch;
                __nv_bfloat162 iH1 = *(__nv_bfloat162*)&hinH[e1];
                __nv_bfloat162 iL1 = *(__nv_bfloat162*)&hinL[e1];
                __nv_bfloat162 iH2 = *(__nv_bfloat162*)&hinH[e2];
                __nv_bfloat162 iL2 = *(__nv_bfloat162*)&hinL[e2];
                float h10 = (d0 + br0 + __bfloat162float(iH1.x) + __bfloat162float(iL1.x)) * SQRT_HALF;
                float h11 = (d1 + br1 + __bfloat162float(iH1.y) + __bfloat162float(iL1.y)) * SQRT_HALF;
                float h20 = (d2 + br0 + __bfloat162float(iH2.x) + __bfloat162float(iL2.x)) * SQRT_HALF;
                float h21 = (d3 + br1 + __bfloat162float(iH2.y) + __bfloat162float(iL2.y)) * SQRT_HALF;
                uint32_t oh1 = packbf2(h10, h11);
                uint32_t oh2 = packbf2(h20, h21);
                __nv_bfloat162 hh1 = *(__nv_bfloat162*)&oh1;
                __nv_bfloat162 hh2 = *(__nv_bfloat162*)&oh2;
                uint32_t ol1 = packbf2(h10 - __bfloat162float(hh1.x), h11 - __bfloat162float(hh1.y));
                uint32_t ol2 = packbf2(h20 - __bfloat162float(hh2.x), h21 - __bfloat162float(hh2.y));
                *(uint32_t*)&houtH[e1] = oh1;
                *(uint32_t*)&houtL[e1] = ol1;
                *(uint32_t*)&houtH[e2] = oh2;
                *(uint32_t*)&houtL[e2] = ol2;
            }
        }
    }
}

// ======================= final head ==========================================
__global__ void final2(const float* __restrict__ skip,
                       const float* __restrict__ Wl1, const float* __restrict__ bl1,
                       const float* __restrict__ Wl2, const float* __restrict__ bl2,
                       float* __restrict__ out) {
    __shared__ float tile[128 * 65];
    __shared__ float b1s[64];
    __shared__ float W2s[64];
    int tid = threadIdx.x;   // 128
    if (tid < 64) { b1s[tid] = bl1[tid]; W2s[tid] = Wl2[tid]; }
    int t0 = (blockIdx.x & 255) * 128;
    int b  = blockIdx.x >> 8;
    for (int i = tid; i < 128 * 64; i += 128) {
        int rr = i >> 6, cc = i & 63;
        tile[rr * 65 + cc] = skip[((size_t)b * TLEN + t0) * 64 + i];
    }
    __syncthreads();
    float s1[64];
    #pragma unroll 8
    for (int j = 0; j < 64; ++j)
        s1[j] = fmaxf(tile[tid * 65 + j] * SQRT_INV_L, 0.f);
    float y2 = bl2[0];
    for (int o = 0; o < 64; ++o) {
        float a = b1s[o];
        #pragma unroll 8
        for (int j = 0; j < 64; ++j) a += Wl1[o * 64 + j] * s1[j];
        y2 += W2s[o] * fmaxf(a, 0.f);
    }
    out[(size_t)b * TLEN + t0 + tid] = y2;
}

// ======================= launch ==============================================
extern "C" void kernel_launch(void* const* d_in, const int* in_sizes, int n_in,
                              void* d_out, int out_size)
{
    const float* x       = (const float*)d_in[0];
    const float* c       = (const float*)d_in[1];
    const float* W_first = (const float*)d_in[2];
    const float* b_first = (const float*)d_in[3];
    const float* W_cin   = (const float*)d_in[4];
    const float* W_up    = (const float*)d_in[5];
    const float* Wd      = (const float*)d_in[6];
    const float* bd      = (const float*)d_in[7];
    const float* Wa      = (const float*)d_in[8];
    const float* Ws      = (const float*)d_in[9];
    const float* bs      = (const float*)d_in[10];
    const float* Wr      = (const float*)d_in[11];
    const float* br      = (const float*)d_in[12];
    const float* Wl1     = (const float*)d_in[13];
    const float* bl1     = (const float*)d_in[14];
    const float* Wl2     = (const float*)d_in[15];
    const float* bl2     = (const float*)d_in[16];
    float* out = (float*)d_out;

    float *skip;
    __nv_bfloat16 *hHa, *hLa, *hHb, *hLb, *cPH, *cPL, *WgH, *WgL, *W2H, *W2L;
    cudaGetSymbolAddress((void**)&skip, g_skip);
    cudaGetSymbolAddress((void**)&hHa,  g_hHa);
    cudaGetSymbolAddress((void**)&hLa,  g_hLa);
    cudaGetSymbolAddress((void**)&hHb,  g_hHb);
    cudaGetSymbolAddress((void**)&hLb,  g_hLb);
    cudaGetSymbolAddress((void**)&cPH,  g_cPH);
    cudaGetSymbolAddress((void**)&cPL,  g_cPL);
    cudaGetSymbolAddress((void**)&WgH,  g_WgH);
    cudaGetSymbolAddress((void**)&WgL,  g_WgL);
    cudaGetSymbolAddress((void**)&W2H,  g_W2H);
    cudaGetSymbolAddress((void**)&W2L,  g_W2L);

    const int COND_SMEM = (80 * 6 + 80 * 8 + 80 * 8 + 80 * 14 + 80 * 36 + 80 * 128) * 4;
    cudaFuncSetAttribute(cond_fused, cudaFuncAttributeMaxDynamicSharedMemorySize, COND_SMEM);
    cudaFuncSetAttribute(layer_mma, cudaFuncAttributeMaxDynamicSharedMemorySize, SMEM_NEED);

    // 1: fused conditioning
    {
        dim3 grid(TLEN / 128, NB);
        cond_fused<<<grid, 256, COND_SMEM>>>(c, W_cin, W_up, cPH, cPL);
    }
    // 2: weight prepack
    {
        int N = NLAYERS * 5 * 128 * 64 + NLAYERS * 128 * 64;
        prepack_w<<<(N + 255) / 256, 256>>>(Wd, Wa, Ws, Wr, WgH, WgL, W2H, W2L);
    }
    // 3: first conv
    {
        int N = NB * TLEN * RC;
        first_pack<<<(N + 255) / 256, 256>>>(x, W_first, b_first, hHa, hLa, skip);
    }
    // 4..33: residual layers
    __nv_bfloat16 *hiH = hHa, *hiL = hLa, *hoH = hHb, *hoL = hLb;
    dim3 grid(TLEN / 128, NB);
    for (int i = 0; i < NLAYERS; ++i) {
        int d = 1 << (i % 10);
        layer_mma<<<grid, 256, SMEM_NEED>>>(i, d, hiH, hiL, hoH, hoL,
                                            cPH, cPL, skip, WgH, WgL, W2H, W2L, bd, bs, br);
        { __nv_bfloat16* t = hiH; hiH = hoH; hoH = t; }
        { __nv_bfloat16* t = hiL; hiL = hoL; hoL = t; }
    }
    // 34: head
    final2<<<NB * (TLEN / 128), 128>>>(skip, Wl1, bl1, Wl2, bl2, out);
}

// round 6
// speedup vs baseline: 4.1263x; 1.0487x over previous
#include <cuda_runtime.h>
#include <cuda_bf16.h>
#include <math.h>
#include <stdint.h>

#define TLEN 32768
#define NB 2
#define RC 64
#define GC 128
#define SC 64
#define AC 80
#define NLAYERS 30
#define SQRT_HALF 0.70710678118654752440f
#define SQRT_INV_L 0.18257418583505537115f

// ======================= scratch (device globals) ============================
__device__ __align__(16) __nv_bfloat16 g_hHa[NB * TLEN * RC];
__device__ __align__(16) __nv_bfloat16 g_hLa[NB * TLEN * RC];
__device__ __align__(16) __nv_bfloat16 g_hHb[NB * TLEN * RC];
__device__ __align__(16) __nv_bfloat16 g_hLb[NB * TLEN * RC];
__device__ float g_skip[NB * TLEN * SC];
__device__ __align__(16) __nv_bfloat16 g_cPH[NB * 2 * TLEN * 64];
__device__ __align__(16) __nv_bfloat16 g_cPL[NB * 2 * TLEN * 64];
__device__ __align__(16) __nv_bfloat16 g_WgH[NLAYERS * 5 * 128 * 64];
__device__ __align__(16) __nv_bfloat16 g_WgL[NLAYERS * 5 * 128 * 64];
__device__ __align__(16) __nv_bfloat16 g_W2H[NLAYERS * 128 * 64];
__device__ __align__(16) __nv_bfloat16 g_W2L[NLAYERS * 128 * 64];

// ======================= helpers =============================================
__device__ __forceinline__ uint32_t smem_u32(const void* p) {
    uint32_t a;
    asm("{ .reg .u64 t; cvta.to.shared.u64 t, %1; cvt.u32.u64 %0, t; }" : "=r"(a) : "l"(p));
    return a;
}
__device__ __forceinline__ void ldm4(uint32_t* r, uint32_t addr) {
    asm volatile("ldmatrix.sync.aligned.m8n8.x4.shared.b16 {%0,%1,%2,%3}, [%4];"
        : "=r"(r[0]), "=r"(r[1]), "=r"(r[2]), "=r"(r[3]) : "r"(addr));
}
__device__ __forceinline__ void mma16816(float* d, const uint32_t* a, uint32_t b0, uint32_t b1) {
    asm volatile("mma.sync.aligned.m16n8k16.row.col.f32.bf16.bf16.f32 "
        "{%0,%1,%2,%3}, {%4,%5,%6,%7}, {%8,%9}, {%0,%1,%2,%3};"
        : "+f"(d[0]), "+f"(d[1]), "+f"(d[2]), "+f"(d[3])
        : "r"(a[0]), "r"(a[1]), "r"(a[2]), "r"(a[3]), "r"(b0), "r"(b1));
}
__device__ __forceinline__ void cpa16(uint32_t dst, const void* src, int srcsz) {
    asm volatile("cp.async.ca.shared.global [%0], [%1], 16, %2;"
        :: "r"(dst), "l"(src), "r"(srcsz) : "memory");
}
#define CP_COMMIT() asm volatile("cp.async.commit_group;" ::: "memory")
#define CP_WAIT0()  asm volatile("cp.async.wait_group 0;" ::: "memory")

__device__ __forceinline__ uint32_t packbf2(float lo, float hi) {
    __nv_bfloat162 t = __floats2bfloat162_rn(lo, hi);
    return *(uint32_t*)&t;
}

// ======================= fused conditioning ==================================
__global__ void cond_fused(const float* __restrict__ c, const float* __restrict__ Wc,
                           const float* __restrict__ Wup,
                           __nv_bfloat16* __restrict__ PH, __nv_bfloat16* __restrict__ PL) {
    extern __shared__ float us[];
    const int b  = blockIdx.y;
    const int t0 = blockIdx.x * 128;
    const int tid = threadIdx.x;   // 256

    const int u0 = (t0 - 4) >> 2;
    const int un = ((t0 + 131) >> 2) - u0 + 1;
    const int v0 = (u0 - 4) >> 2;
    const int vn = ((u0 + un - 1 + 4) >> 2) - v0 + 1;
    const int w0 = (v0 - 4) >> 2;
    const int wn = ((v0 + vn - 1 + 4) >> 2) - w0 + 1;
    const int f0 = (w0 - 4) >> 2;
    const int fn = ((w0 + wn - 1 + 4) >> 2) - f0 + 1;

    float* y0 = us;
    float* y1 = y0 + 80 * 6;
    float* s1 = y1 + 80 * 8;
    float* s2 = s1 + 80 * 8;
    float* s3 = s2 + 80 * 14;
    float* s4 = s3 + 80 * 36;

    for (int i = tid; i < 80 * fn; i += 256) {
        int ch = i / fn, ff = i - ch * fn;
        int f = f0 + ff;
        y0[ch * 6 + ff] = (f >= 0 && f < 128) ? c[((size_t)b * 80 + ch) * 128 + f] : 0.f;
    }
    __syncthreads();
    for (int i = tid; i < 80 * fn; i += 256) {
        int o = i / fn, ff = i - o * fn;
        float acc = 0.f;
        #pragma unroll 4
        for (int k = 0; k < 80; ++k) acc += Wc[o * 80 + k] * y0[k * 6 + ff];
        y1[o * 8 + ff] = acc;
    }
    __syncthreads();
    for (int i = tid; i < 80 * wn; i += 256) {
        int o = i / wn, wi = i - o * wn;
        int w = w0 + wi;
        float acc = 0.f;
        #pragma unroll
        for (int k = 0; k < 9; ++k) {
            int rr = w - 4 + k;
            if (rr >= 0 && rr < 512) acc += Wup[k] * y1[o * 8 + ((rr >> 2) - f0)];
        }
        s1[o * 8 + wi] = acc;
    }
    __syncthreads();
    for (int i = tid; i < 80 * vn; i += 256) {
        int o = i / vn, vi = i - o * vn;
        int v = v0 + vi;
        float acc = 0.f;
        #pragma unroll
        for (int k = 0; k < 9; ++k) {
            int rr = v - 4 + k;
            if (rr >= 0 && rr < 2048) acc += Wup[9 + k] * s1[o * 8 + ((rr >> 2) - w0)];
        }
        s2[o * 14 + vi] = acc;
    }
    __syncthreads();
    for (int i = tid; i < 80 * un; i += 256) {
        int o = i / un, ui = i - o * un;
        int u = u0 + ui;
        float acc = 0.f;
        #pragma unroll
        for (int k = 0; k < 9; ++k) {
            int rr = u - 4 + k;
            if (rr >= 0 && rr < 8192) acc += Wup[18 + k] * s2[o * 14 + ((rr >> 2) - v0)];
        }
        s3[o * 36 + ui] = acc;
    }
    __syncthreads();
    for (int i = tid; i < 80 * 128; i += 256) {
        int o = i >> 7, tl = i & 127;
        int t = t0 + tl;
        float acc = 0.f;
        #pragma unroll
        for (int k = 0; k < 9; ++k) {
            int rr = t - 4 + k;
            if (rr >= 0 && rr < TLEN) acc += Wup[27 + k] * s3[o * 36 + ((rr >> 2) - u0)];
        }
        s4[o * 128 + tl] = acc;
    }
    __syncthreads();
    for (int i = tid; i < 128 * 64; i += 256) {
        int tl = i >> 6, j = i & 63;
        size_t o0 = (((size_t)b * 2 + 0) * TLEN + (t0 + tl)) * 64 + j;
        size_t o1 = (((size_t)b * 2 + 1) * TLEN + (t0 + tl)) * 64 + j;
        float v0f = s4[j * 128 + tl];
        float v1f = (j < 16) ? s4[(64 + j) * 128 + tl] : 0.f;
        __nv_bfloat16 h0 = __float2bfloat16(v0f);
        __nv_bfloat16 h1 = __float2bfloat16(v1f);
        PH[o0] = h0;  PL[o0] = __float2bfloat16(v0f - __bfloat162float(h0));
        PH[o1] = h1;  PL[o1] = __float2bfloat16(v1f - __bfloat162float(h1));
    }
}

// ======================= weight prepack ======================================
__global__ void prepack_w(const float* __restrict__ Wd, const float* __restrict__ Wa,
                          const float* __restrict__ Ws, const float* __restrict__ Wr,
                          __nv_bfloat16* __restrict__ WgH, __nv_bfloat16* __restrict__ WgL,
                          __nv_bfloat16* __restrict__ W2H, __nv_bfloat16* __restrict__ W2L) {
    const int N1 = NLAYERS * 5 * 128 * 64;
    const int N2 = NLAYERS * 128 * 64;
    int i = blockIdx.x * blockDim.x + threadIdx.x;
    if (i < N1) {
        int kl = i & 63;
        int r  = (i >> 6) & 127;
        int lc = i >> 13;
        int cc = lc % 5;
        int l  = lc / 5;
        int j  = ((r >> 4) << 3) + (((r & 7) >> 1) << 1) + ((r >> 3) & 1);
        int ch = (r & 1) ? (64 + j) : j;
        float w;
        if (cc < 3)       w = Wd[(((size_t)l * GC + ch) * RC + kl) * 3 + cc];
        else if (cc == 3) w = Wa[((size_t)l * GC + ch) * AC + kl];
        else              w = (kl < AC - 64) ? Wa[((size_t)l * GC + ch) * AC + 64 + kl] : 0.f;
        __nv_bfloat16 h = __float2bfloat16(w);
        WgH[i] = h;
        WgL[i] = __float2bfloat16(w - __bfloat162float(h));
    } else if (i - N1 < N2) {
        int i2 = i - N1;
        int k  = i2 & 63;
        int r2 = (i2 >> 6) & 127;
        int l  = i2 >> 13;
        float w = (r2 < 64) ? Ws[((size_t)l * SC + r2) * 64 + k]
                            : Wr[((size_t)l * RC + (r2 - 64)) * 64 + k];
        __nv_bfloat16 h = __float2bfloat16(w);
        W2H[i2] = h;
        W2L[i2] = __float2bfloat16(w - __bfloat162float(h));
    }
}

__global__ void first_pack(const float* __restrict__ x,
                           const float* __restrict__ Wf, const float* __restrict__ bf,
                           __nv_bfloat16* __restrict__ hH, __nv_bfloat16* __restrict__ hL,
                           float* __restrict__ skip) {
    int idx = blockIdx.x * blockDim.x + threadIdx.x;
    if (idx >= NB * TLEN * RC) return;
    int j = idx & 63;
    int t = (idx >> 6) & (TLEN - 1);
    int b = idx >> 21;
    float v = Wf[j] * x[(size_t)b * TLEN + t] + bf[j];
    __nv_bfloat16 h = __float2bfloat16(v);
    hH[idx] = h;
    hL[idx] = __float2bfloat16(v - __bfloat162float(h));
    skip[idx] = 0.f;
}

// ======================= fused residual layer ================================
#define STRIDE 144
#define OFF_WH  0
#define OFF_WL  (128 * STRIDE)
#define OFF_DH  (2 * 128 * STRIDE)
#define OFF_DL  (3 * 128 * STRIDE)
#define OFF_BD  (4 * 128 * STRIDE)
#define SMEM_NEED (OFF_BD + 1024)

__global__ __launch_bounds__(256, 2)
void layer_mma(int l, int dil,
               const __nv_bfloat16* __restrict__ hinH, const __nv_bfloat16* __restrict__ hinL,
               __nv_bfloat16* __restrict__ houtH, __nv_bfloat16* __restrict__ houtL,
               const __nv_bfloat16* __restrict__ cPH, const __nv_bfloat16* __restrict__ cPL,
               float* __restrict__ skip,
               const __nv_bfloat16* __restrict__ WgH, const __nv_bfloat16* __restrict__ WgL,
               const __nv_bfloat16* __restrict__ W2H, const __nv_bfloat16* __restrict__ W2L,
               const float* __restrict__ bd, const float* __restrict__ bs,
               const float* __restrict__ br) {
    extern __shared__ char smem_c[];
    const uint32_t sb = smem_u32(smem_c);
    float* sbd = (float*)(smem_c + OFF_BD);

    const int tid  = threadIdx.x;
    const int warp = tid >> 5;
    const int lane = tid & 31;
    const int b    = blockIdx.y;
    const int t0   = blockIdx.x * 128;
    const int mbase = warp * 16;

    const int lrow  = lane & 15;
    const int lkoff = (lane >> 4) * 16;
    const int q     = lane & 3;
    const int r     = lane >> 2;

    // biases into smem: bd[0..127], bs[128..191], br[192..255]
    if (tid < 128)      sbd[tid] = bd[l * GC + tid];
    else if (tid < 192) sbd[tid] = bs[l * SC + tid - 128];
    else                sbd[tid] = br[l * RC + tid - 192];

    // ---- chunk staging via cp.async ----
    auto stage_chunk = [&](int c) {
        const char* wHb = (const char*)(WgH + (((size_t)l * 5 + c) * 128) * 64);
        const char* wLb = (const char*)(WgL + (((size_t)l * 5 + c) * 128) * 64);
        #pragma unroll
        for (int it = 0; it < 4; ++it) {
            const int p = it * 256 + tid;
            const int row = p >> 3, j = p & 7;
            if (c == 4 && j >= 2) continue;
            const uint32_t d = (uint32_t)row * STRIDE + j * 16;
            cpa16(sb + OFF_WH + d, wHb + p * 16, 16);
            cpa16(sb + OFF_WL + d, wLb + p * 16, 16);
            const char* srcH;
            const char* srcL;
            int sz = 16;
            if (c < 3) {
                int tg = t0 + row + (c - 1) * dil;
                if (tg >= 0 && tg < TLEN) {
                    size_t e = ((size_t)b * TLEN + tg) * 128 + j * 16;
                    srcH = (const char*)hinH + e;
                    srcL = (const char*)hinL + e;
                } else { srcH = (const char*)hinH; srcL = (const char*)hinL; sz = 0; }
            } else {
                size_t e = (((size_t)b * 2 + (c - 3)) * TLEN + (t0 + row)) * 128 + j * 16;
                srcH = (const char*)cPH + e;
                srcL = (const char*)cPL + e;
            }
            cpa16(sb + OFF_DH + d, srcH, sz);
            cpa16(sb + OFF_DL + d, srcL, sz);
        }
        CP_COMMIT();
    };

    stage_chunk(0);

    float acc[16][4];
    #pragma unroll
    for (int i = 0; i < 16; ++i)
        #pragma unroll
        for (int j2 = 0; j2 < 4; ++j2) acc[i][j2] = 0.f;

    // ---------------- GEMM1: D1[t][gch] ----------------
    for (int c = 0; c < 5; ++c) {
        CP_WAIT0();
        __syncthreads();
        const int nks = (c == 4) ? 1 : 4;
        const uint32_t a_base = sb + (uint32_t)(mbase + lrow) * STRIDE + lkoff;
        for (int ks = 0; ks < nks; ++ks) {
            uint32_t ah[4], al[4];
            ldm4(ah, a_base + OFF_DH + ks * 32);
            ldm4(al, a_base + OFF_DL + ks * 32);
            #pragma unroll
            for (int g = 0; g < 2; ++g) {
                uint32_t bh[4][4], bl[4][4];
                #pragma unroll
                for (int i = 0; i < 4; ++i) {
                    uint32_t baddr = sb + (uint32_t)((g * 4 + i) * 16 + lrow) * STRIDE
                                   + lkoff + ks * 32;
                    ldm4(bh[i], baddr + OFF_WH);
                    ldm4(bl[i], baddr + OFF_WL);
                }
                #pragma unroll
                for (int i = 0; i < 4; ++i) {
                    mma16816(acc[(g * 4 + i) * 2],     ah, bh[i][0], bh[i][2]);
                    mma16816(acc[(g * 4 + i) * 2 + 1], ah, bh[i][1], bh[i][3]);
                }
                #pragma unroll
                for (int i = 0; i < 4; ++i) {
                    mma16816(acc[(g * 4 + i) * 2],     ah, bl[i][0], bl[i][2]);
                    mma16816(acc[(g * 4 + i) * 2 + 1], ah, bl[i][1], bl[i][3]);
                }
                #pragma unroll
                for (int i = 0; i < 4; ++i) {
                    mma16816(acc[(g * 4 + i) * 2],     al, bh[i][0], bh[i][2]);
                    mma16816(acc[(g * 4 + i) * 2 + 1], al, bh[i][1], bh[i][3]);
                }
            }
        }
        __syncthreads();
        if (c < 4) stage_chunk(c + 1);
    }

    // stage W2 (overlaps gate)
    {
        const char* wHb = (const char*)(W2H + (size_t)l * 128 * 64);
        const char* wLb = (const char*)(W2L + (size_t)l * 128 * 64);
        #pragma unroll
        for (int it = 0; it < 4; ++it) {
            const int p = it * 256 + tid;
            const int row = p >> 3, j = p & 7;
            const uint32_t d = (uint32_t)row * STRIDE + j * 16;
            cpa16(sb + OFF_WH + d, wHb + p * 16, 16);
            cpa16(sb + OFF_WL + d, wLb + p * 16, 16);
        }
        CP_COMMIT();
    }

    // ---------------- gate (registers only) ----------------
    uint32_t zhA[8], zlA[8], zhB[8], zlB[8];
    #pragma unroll
    for (int nt = 0; nt < 8; ++nt) {
        float zA[2], zB[2];
        #pragma unroll
        for (int s = 0; s < 2; ++s) {
            int j = nt * 8 + 2 * q + s;
            float ba = sbd[j], bb = sbd[64 + j];
            #pragma unroll
            for (int h = 0; h < 2; ++h) {
                float xa = acc[nt * 2 + s][h * 2 + 0] + ba;
                float xb = acc[nt * 2 + s][h * 2 + 1] + bb;
                float e2 = __expf(-2.f * fabsf(xa));
                float th = copysignf(__fdividef(1.f - e2, 1.f + e2), xa);
                float sg = __fdividef(1.f, 1.f + __expf(-xb));
                float z = th * sg;
                if (h == 0) zA[s] = z; else zB[s] = z;
            }
        }
        zhA[nt] = packbf2(zA[0], zA[1]);
        zhB[nt] = packbf2(zB[0], zB[1]);
        __nv_bfloat162 hA = *(__nv_bfloat162*)&zhA[nt];
        __nv_bfloat162 hB = *(__nv_bfloat162*)&zhB[nt];
        zlA[nt] = packbf2(zA[0] - __bfloat162float(hA.x), zA[1] - __bfloat162float(hA.y));
        zlB[nt] = packbf2(zB[0] - __bfloat162float(hB.x), zB[1] - __bfloat162float(hB.y));
    }

    CP_WAIT0();
    __syncthreads();

    // ---------------- GEMM2: D2[t][och] = z(t x 64) * W2^T ----------------
    float acc2[16][4];
    #pragma unroll
    for (int i = 0; i < 16; ++i)
        #pragma unroll
        for (int j2 = 0; j2 < 4; ++j2) acc2[i][j2] = 0.f;

    #pragma unroll
    for (int ks = 0; ks < 4; ++ks) {
        uint32_t azh[4] = {zhA[2 * ks], zhB[2 * ks], zhA[2 * ks + 1], zhB[2 * ks + 1]};
        uint32_t azl[4] = {zlA[2 * ks], zlB[2 * ks], zlA[2 * ks + 1], zlB[2 * ks + 1]};
        #pragma unroll
        for (int g = 0; g < 2; ++g) {
            uint32_t wh[4][4], wl[4][4];
            #pragma unroll
            for (int i = 0; i < 4; ++i) {
                uint32_t baddr = sb + (uint32_t)((g * 4 + i) * 16 + lrow) * STRIDE
                               + lkoff + ks * 32;
                ldm4(wh[i], baddr + OFF_WH);
                ldm4(wl[i], baddr + OFF_WL);
            }
            #pragma unroll
            for (int i = 0; i < 4; ++i) {
                mma16816(acc2[(g * 4 + i) * 2],     azh, wh[i][0], wh[i][2]);
                mma16816(acc2[(g * 4 + i) * 2 + 1], azh, wh[i][1], wh[i][3]);
            }
            #pragma unroll
            for (int i = 0; i < 4; ++i) {
                mma16816(acc2[(g * 4 + i) * 2],     azh, wl[i][0], wl[i][2]);
                mma16816(acc2[(g * 4 + i) * 2 + 1], azh, wl[i][1], wl[i][3]);
            }
            #pragma unroll
            for (int i = 0; i < 4; ++i) {
                mma16816(acc2[(g * 4 + i) * 2],     azl, wh[i][0], wh[i][2]);
                mma16816(acc2[(g * 4 + i) * 2 + 1], azl, wh[i][1], wh[i][3]);
            }
        }
    }

    // ---------------- epilogue (coalesced [t][ch]) ----------------
    const int trowA = t0 + mbase + r;
    const int trowB = trowA + 8;
    #pragma unroll
    for (int nt = 0; nt < 8; ++nt) {
        #pragma unroll
        for (int s = 0; s < 2; ++s) {
            int cch = nt * 16 + s * 8 + 2 * q;
            float d0 = acc2[nt * 2 + s][0], d1 = acc2[nt * 2 + s][1];
            float d2 = acc2[nt * 2 + s][2], d3 = acc2[nt * 2 + s][3];
            if (cch < 64) {
                float bs0 = sbd[128 + cch], bs1 = sbd[128 + cch + 1];
                float2* p1 = (float2*)&skip[((size_t)b * TLEN + trowA) * 64 + cch];
                float2* p2 = (float2*)&skip[((size_t)b * TLEN + trowB) * 64 + cch];
                float2 v1 = *p1, v2 = *p2;
                v1.x += d0 + bs0; v1.y += d1 + bs1;
                v2.x += d2 + bs0; v2.y += d3 + bs1;
                *p1 = v1; *p2 = v2;
            } else {
                int ch = cch - 64;
                float br0 = sbd[192 + ch], br1 = sbd[192 + ch + 1];
                size_t e1 = ((size_t)b * TLEN + trowA) * 64 + ch;
                size_t e2 = ((size_t)b * TLEN + trowB) * 64 + ch;
                __nv_bfloat162 iH1 = *(__nv_bfloat162*)&hinH[e1];
                __nv_bfloat162 iL1 = *(__nv_bfloat162*)&hinL[e1];
                __nv_bfloat162 iH2 = *(__nv_bfloat162*)&hinH[e2];
                __nv_bfloat162 iL2 = *(__nv_bfloat162*)&hinL[e2];
                float h10 = (d0 + br0 + __bfloat162float(iH1.x) + __bfloat162float(iL1.x)) * SQRT_HALF;
                float h11 = (d1 + br1 + __bfloat162float(iH1.y) + __bfloat162float(iL1.y)) * SQRT_HALF;
                float h20 = (d2 + br0 + __bfloat162float(iH2.x) + __bfloat162float(iL2.x)) * SQRT_HALF;
                float h21 = (d3 + br1 + __bfloat162float(iH2.y) + __bfloat162float(iL2.y)) * SQRT_HALF;
                uint32_t oh1 = packbf2(h10, h11);
                uint32_t oh2 = packbf2(h20, h21);
                __nv_bfloat162 hh1 = *(__nv_bfloat162*)&oh1;
                __nv_bfloat162 hh2 = *(__nv_bfloat162*)&oh2;
                uint32_t ol1 = packbf2(h10 - __bfloat162float(hh1.x), h11 - __bfloat162float(hh1.y));
                uint32_t ol2 = packbf2(h20 - __bfloat162float(hh2.x), h21 - __bfloat162float(hh2.y));
                *(uint32_t*)&houtH[e1] = oh1;
                *(uint32_t*)&houtL[e1] = ol1;
                *(uint32_t*)&houtH[e2] = oh2;
                *(uint32_t*)&houtL[e2] = ol2;
            }
        }
    }
}

// ======================= final head ==========================================
__global__ void final2(const float* __restrict__ skip,
                       const float* __restrict__ Wl1, const float* __restrict__ bl1,
                       const float* __restrict__ Wl2, const float* __restrict__ bl2,
                       float* __restrict__ out) {
    __shared__ float tile[128 * 65];
    __shared__ float b1s[64];
    __shared__ float W2s[64];
    int tid = threadIdx.x;   // 128
    if (tid < 64) { b1s[tid] = bl1[tid]; W2s[tid] = Wl2[tid]; }
    int t0 = (blockIdx.x & 255) * 128;
    int b  = blockIdx.x >> 8;
    for (int i = tid; i < 128 * 64; i += 128) {
        int rr = i >> 6, cc = i & 63;
        tile[rr * 65 + cc] = skip[((size_t)b * TLEN + t0) * 64 + i];
    }
    __syncthreads();
    float s1[64];
    #pragma unroll 8
    for (int j = 0; j < 64; ++j)
        s1[j] = fmaxf(tile[tid * 65 + j] * SQRT_INV_L, 0.f);
    float y2 = bl2[0];
    for (int o = 0; o < 64; ++o) {
        float a = b1s[o];
        #pragma unroll 8
        for (int j = 0; j < 64; ++j) a += Wl1[o * 64 + j] * s1[j];
        y2 += W2s[o] * fmaxf(a, 0.f);
    }
    out[(size_t)b * TLEN + t0 + tid] = y2;
}

// ======================= launch ==============================================
extern "C" void kernel_launch(void* const* d_in, const int* in_sizes, int n_in,
                              void* d_out, int out_size)
{
    const float* x       = (const float*)d_in[0];
    const float* c       = (const float*)d_in[1];
    const float* W_first = (const float*)d_in[2];
    const float* b_first = (const float*)d_in[3];
    const float* W_cin   = (const float*)d_in[4];
    const float* W_up    = (const float*)d_in[5];
    const float* Wd      = (const float*)d_in[6];
    const float* bd      = (const float*)d_in[7];
    const float* Wa      = (const float*)d_in[8];
    const float* Ws      = (const float*)d_in[9];
    const float* bs      = (const float*)d_in[10];
    const float* Wr      = (const float*)d_in[11];
    const float* br      = (const float*)d_in[12];
    const float* Wl1     = (const float*)d_in[13];
    const float* bl1     = (const float*)d_in[14];
    const float* Wl2     = (const float*)d_in[15];
    const float* bl2     = (const float*)d_in[16];
    float* out = (float*)d_out;

    float *skip;
    __nv_bfloat16 *hHa, *hLa, *hHb, *hLb, *cPH, *cPL, *WgH, *WgL, *W2H, *W2L;
    cudaGetSymbolAddress((void**)&skip, g_skip);
    cudaGetSymbolAddress((void**)&hHa,  g_hHa);
    cudaGetSymbolAddress((void**)&hLa,  g_hLa);
    cudaGetSymbolAddress((void**)&hHb,  g_hHb);
    cudaGetSymbolAddress((void**)&hLb,  g_hLb);
    cudaGetSymbolAddress((void**)&cPH,  g_cPH);
    cudaGetSymbolAddress((void**)&cPL,  g_cPL);
    cudaGetSymbolAddress((void**)&WgH,  g_WgH);
    cudaGetSymbolAddress((void**)&WgL,  g_WgL);
    cudaGetSymbolAddress((void**)&W2H,  g_W2H);
    cudaGetSymbolAddress((void**)&W2L,  g_W2L);

    const int COND_SMEM = (80 * 6 + 80 * 8 + 80 * 8 + 80 * 14 + 80 * 36 + 80 * 128) * 4;
    cudaFuncSetAttribute(cond_fused, cudaFuncAttributeMaxDynamicSharedMemorySize, COND_SMEM);
    cudaFuncSetAttribute(layer_mma, cudaFuncAttributeMaxDynamicSharedMemorySize, SMEM_NEED);

    {
        dim3 grid(TLEN / 128, NB);
        cond_fused<<<grid, 256, COND_SMEM>>>(c, W_cin, W_up, cPH, cPL);
    }
    {
        int N = NLAYERS * 5 * 128 * 64 + NLAYERS * 128 * 64;
        prepack_w<<<(N + 255) / 256, 256>>>(Wd, Wa, Ws, Wr, WgH, WgL, W2H, W2L);
    }
    {
        int N = NB * TLEN * RC;
        first_pack<<<(N + 255) / 256, 256>>>(x, W_first, b_first, hHa, hLa, skip);
    }
    __nv_bfloat16 *hiH = hHa, *hiL = hLa, *hoH = hHb, *hoL = hLb;
    dim3 grid(TLEN / 128, NB);
    for (int i = 0; i < NLAYERS; ++i) {
        int d = 1 << (i % 10);
        layer_mma<<<grid, 256, SMEM_NEED>>>(i, d, hiH, hiL, hoH, hoL,
                                            cPH, cPL, skip, WgH, WgL, W2H, W2L, bd, bs, br);
        { __nv_bfloat16* t = hiH; hiH = hoH; hoH = t; }
        { __nv_bfloat16* t = hiL; hiL = hoL; hoL = t; }
    }
    final2<<<NB * (TLEN / 128), 128>>>(skip, Wl1, bl1, Wl2, bl2, out);
}